// round 13
// baseline (speedup 1.0000x reference)
#include <cuda_runtime.h>
#include <cuda_fp16.h>
#include <math.h>
#include <stdint.h>

#define DIM 128
#define NITER 8

#define MAXL 100096ull
#define MAXC 150016ull
#define MAXE 450048

// ---------------- fp16 intermediates ----------------
__device__ __half g_lfeat[MAXL * 128];
__device__ __half g_cfeat[MAXC * 128];
__device__ __half g_caggr[MAXC * 128];
__device__ __half g_lx0  [MAXL * 128];
__device__ __half g_l2lm [MAXL * 128];
__device__ int   g_lei32[MAXE];
__device__ int   g_cei32[MAXE];

// ---------------- CSR scratch ----------------
#define MAXT (MAXC + MAXL + 2)
__device__ int g_cnt [MAXT];
__device__ int g_off [MAXT];
__device__ int g_cur [MAXT];
__device__ int g_permc[MAXE];
__device__ int g_perml[MAXE];

// ---------------- fp16 state + weights ----------------
__device__ __half g_l16[MAXL * 128];
__device__ __half g_c16[MAXC * 128];
__device__ __half g_mw16[98304];
__device__ __half g_gw16[245760];
__device__ float  g_bcat_c[512], g_bcat_l[512];

#define OFF_WRZC 0
#define OFF_WINC 65536
#define OFF_WHNC 81920
#define OFF_WRZL 98304
#define OFF_WINL 196608
#define OFF_WHNL 229376

// =================== helpers ===================
__device__ __forceinline__ uint32_t smem_to_u32(const void* p) {
    uint32_t a;
    asm("{ .reg .u64 t; cvta.to.shared.u64 t, %1; cvt.u32.u64 %0, t; }"
        : "=r"(a) : "l"(p));
    return a;
}
__device__ __forceinline__ void cp16(uint32_t dst, const void* src, int sz) {
    asm volatile("cp.async.cg.shared.global [%0], [%1], 16, %2;"
                 :: "r"(dst), "l"(src), "r"(sz));
}
#define CP_COMMIT() asm volatile("cp.async.commit_group;" ::: "memory")
#define CP_WAIT0()  asm volatile("cp.async.wait_group 0;" ::: "memory")
#define CP_WAIT1()  asm volatile("cp.async.wait_group 1;" ::: "memory")

__device__ __forceinline__ void ldx4(uint32_t* r, uint32_t addr) {
    asm volatile("ldmatrix.sync.aligned.m8n8.x4.shared.b16 {%0,%1,%2,%3}, [%4];"
                 : "=r"(r[0]), "=r"(r[1]), "=r"(r[2]), "=r"(r[3]) : "r"(addr));
}
__device__ __forceinline__ void ldx2(uint32_t* r, uint32_t addr) {
    asm volatile("ldmatrix.sync.aligned.m8n8.x2.shared.b16 {%0,%1}, [%2];"
                 : "=r"(r[0]), "=r"(r[1]) : "r"(addr));
}
__device__ __forceinline__ void mma_f16(float* d, const uint32_t* a, const uint32_t* b) {
    asm volatile("mma.sync.aligned.m16n8k16.row.col.f32.f16.f16.f32 "
                 "{%0,%1,%2,%3}, {%4,%5,%6,%7}, {%8,%9}, {%0,%1,%2,%3};"
                 : "+f"(d[0]), "+f"(d[1]), "+f"(d[2]), "+f"(d[3])
                 : "r"(a[0]), "r"(a[1]), "r"(a[2]), "r"(a[3]), "r"(b[0]), "r"(b[1]));
}
__device__ __forceinline__ uint32_t packh2(float x, float y) {
    __half2 p = __floats2half2_rn(x, y);
    return *(uint32_t*)&p;
}
__device__ __forceinline__ float sigm(float x) { return 1.f / (1.f + expf(-x)); }

#define REG 18432u
#define SMEM_GRU (4 * REG)      // A0 A1 W0 W1
#define SMEM_MLP (6 * REG)      // A0 A1 W0 W1 H0 H1

__device__ __forceinline__ void compute_chunk(float acc[4][4][4],
                                              uint32_t aBase, uint32_t wBase)
{
    #pragma unroll
    for (int k16 = 0; k16 < 4; k16++) {
        const uint32_t kb = k16 << 5;
        uint32_t af[4][4];
        #pragma unroll
        for (int mi = 0; mi < 4; mi++)
            ldx4(af[mi], aBase + mi * (16 * 144) + kb);
        #pragma unroll
        for (int ni = 0; ni < 4; ni++) {
            uint32_t bf[2];
            ldx2(bf, wBase + ni * (8 * 144) + kb);
            #pragma unroll
            for (int mi = 0; mi < 4; mi++)
                mma_f16(acc[mi][ni], af[mi], bf);
        }
    }
}

// =================== merged 3x fused 2-layer MLP ===================
struct MlpP {
    const __half* A; const __half* W1; const __half* W2;
    const float* b1; const float* b2;
    __half* out; int N; int xr;
};

__global__ __launch_bounds__(256, 2)
void fused_mlp3(MlpP p0, MlpP p1, MlpP p2)
{
    extern __shared__ char smem[];
    const MlpP P = (blockIdx.y == 0) ? p0 : (blockIdx.y == 1) ? p1 : p2;
    const int bm = blockIdx.x * 128;
    if (bm >= P.N) return;

    const uint32_t sb = smem_to_u32(smem);
    const int tid  = threadIdx.x;
    const int lane = tid & 31;
    const int wid  = tid >> 5;
    const int wm   = wid >> 2;
    const int wn   = wid & 3;

    const uint32_t aOff = (uint32_t)(wm * 64 + (lane & 15)) * 144 + ((lane >> 4) << 4);
    const uint32_t bOff = (uint32_t)(wn * 32 + (lane & 7)) * 144 + (((lane >> 3) & 1) << 4);
    const int lrow[4] = { tid >> 3, (tid + 256) >> 3, (tid + 512) >> 3, (tid + 768) >> 3 };
    const int lunit   = tid & 7;

    float acc[4][4][4] = {};

    auto issue1 = [&](int kc) {
        const uint32_t aBuf = sb + (uint32_t)(kc & 1) * REG;
        const uint32_t wBuf = sb + (2u + (kc & 1)) * REG;
        const int k0 = kc << 6;
        #pragma unroll
        for (int t = 0; t < 4; t++) {
            int row = lrow[t];
            uint32_t so = (uint32_t)row * 144 + (lunit << 4);
            int grow = bm + row;
            int ok = grow < P.N;
            int sr = ok ? (P.xr ? (grow ^ 1) : grow) : 0;
            cp16(aBuf + so, P.A + (size_t)sr * 128 + k0 + lunit * 8, ok ? 16 : 0);
            cp16(wBuf + so, P.W1 + (size_t)row * 128 + k0 + lunit * 8, 16);
        }
        CP_COMMIT();
    };

    issue1(0);
    issue1(1);
    CP_WAIT1(); __syncthreads();
    compute_chunk(acc, sb + aOff, sb + 2 * REG + bOff);
    CP_WAIT0(); __syncthreads();
    compute_chunk(acc, sb + REG + aOff, sb + 3 * REG + bOff);
    __syncthreads();

    // prefetch W2 into W0/W1
    #pragma unroll
    for (int kc = 0; kc < 2; kc++) {
        const uint32_t wBuf = sb + (2u + kc) * REG;
        const int k0 = kc << 6;
        #pragma unroll
        for (int t = 0; t < 4; t++) {
            int row = lrow[t];
            uint32_t so = (uint32_t)row * 144 + (lunit << 4);
            cp16(wBuf + so, P.W2 + (size_t)row * 128 + k0 + lunit * 8, 16);
        }
    }
    CP_COMMIT();

    // epilogue 1: relu -> hid H0/H1
    #pragma unroll
    for (int ni = 0; ni < 4; ni++) {
        int c = wn * 32 + ni * 8 + ((lane & 3) << 1);
        float2 bv = *(const float2*)(P.b1 + c);
        uint32_t roff = (4u + (uint32_t)(c >> 6)) * REG + (uint32_t)(c & 63) * 2;
        #pragma unroll
        for (int mi = 0; mi < 4; mi++) {
            int rl0 = wm * 64 + mi * 16 + (lane >> 2);
            float vx0 = fmaxf(acc[mi][ni][0] + bv.x, 0.f);
            float vy0 = fmaxf(acc[mi][ni][1] + bv.y, 0.f);
            float vx1 = fmaxf(acc[mi][ni][2] + bv.x, 0.f);
            float vy1 = fmaxf(acc[mi][ni][3] + bv.y, 0.f);
            *(uint32_t*)(smem + roff + (uint32_t)rl0 * 144)       = packh2(vx0, vy0);
            *(uint32_t*)(smem + roff + (uint32_t)(rl0 + 8) * 144) = packh2(vx1, vy1);
            acc[mi][ni][0] = acc[mi][ni][1] = acc[mi][ni][2] = acc[mi][ni][3] = 0.f;
        }
    }
    CP_WAIT0(); __syncthreads();

    compute_chunk(acc, sb + 4 * REG + aOff, sb + 2 * REG + bOff);
    compute_chunk(acc, sb + 5 * REG + aOff, sb + 3 * REG + bOff);

    #pragma unroll
    for (int ni = 0; ni < 4; ni++) {
        int c = wn * 32 + ni * 8 + ((lane & 3) << 1);
        float2 bv = *(const float2*)(P.b2 + c);
        #pragma unroll
        for (int mi = 0; mi < 4; mi++) {
            int r0 = bm + wm * 64 + mi * 16 + (lane >> 2);
            if (r0 < P.N)
                *(uint32_t*)(P.out + (size_t)r0 * 128 + c) =
                    packh2(acc[mi][ni][0] + bv.x, acc[mi][ni][1] + bv.y);
            if (r0 + 8 < P.N)
                *(uint32_t*)(P.out + (size_t)(r0 + 8) * 128 + c) =
                    packh2(acc[mi][ni][2] + bv.x, acc[mi][ni][3] + bv.y);
        }
    }
}

// =================== fully fused GRU ===================
// One CTA = 128 node rows. Sequential GEMM tiles r,z,i,hn (gates stay in regs),
// fused pointwise epilogue. Clause blocks [0,gcC), literal blocks after.
struct GruP {
    const __half* ax[2]; int nx;   // x sources (128 cols each)
    const __half* h16;
    const __half* Wrz; const __half* Win; const __half* Whn;
    const float* bias;             // [rz(256) | i(128) | hn(128)]
    const float* hcur; float* hout; __half* h16o;
    int N;
};

__global__ __launch_bounds__(256, 1)
void fused_gru(GruP Pc, GruP Pl, int gcC)
{
    extern __shared__ char smem[];
    const bool isC = (int)blockIdx.x < gcC;
    const GruP P = isC ? Pc : Pl;
    const int bm = (isC ? blockIdx.x : blockIdx.x - gcC) * 128;
    if (bm >= P.N) return;

    const uint32_t sb = smem_to_u32(smem);
    const int tid  = threadIdx.x;
    const int lane = tid & 31;
    const int wid  = tid >> 5;
    const int wm   = wid >> 2;
    const int wn   = wid & 3;

    const uint32_t aOff = (uint32_t)(wm * 64 + (lane & 15)) * 144 + ((lane >> 4) << 4);
    const uint32_t bOff = (uint32_t)(wn * 32 + (lane & 7)) * 144 + (((lane >> 3) & 1) << 4);
    const int lrow[4] = { tid >> 3, (tid + 256) >> 3, (tid + 512) >> 3, (tid + 768) >> 3 };
    const int lunit   = tid & 7;

    const __half* srz[3];
    srz[0] = P.ax[0];
    srz[1] = (P.nx == 2) ? P.ax[1] : P.h16;
    srz[2] = P.h16;
    const int nrz = P.nx + 1;
    const int Krz = nrz * 128;
    const int Kin = P.nx * 128;

    float acc[4][4][4];
    uint32_t rreg[32], zreg[32], ireg[32];

    auto issue = [&](const __half* const* S, const __half* W, int wrow, int Kst, int kc) {
        const uint32_t aBuf = sb + (uint32_t)(kc & 1) * REG;
        const uint32_t wBuf = sb + (2u + (kc & 1)) * REG;
        const __half* srcBase = S[kc >> 1];
        const int colOfs = ((kc & 1) << 6) + lunit * 8;
        const int k0 = kc << 6;
        #pragma unroll
        for (int t = 0; t < 4; t++) {
            int row = lrow[t];
            uint32_t so = (uint32_t)row * 144 + (lunit << 4);
            int grow = bm + row;
            int ok = grow < P.N;
            cp16(aBuf + so, srcBase + (size_t)(ok ? grow : 0) * 128 + colOfs, ok ? 16 : 0);
            cp16(wBuf + so, W + (size_t)(wrow + row) * Kst + k0 + lunit * 8, 16);
        }
        CP_COMMIT();
    };

    auto run_tile = [&](const __half* const* S, int nchunk, const __half* W, int wrow, int Kst) {
        #pragma unroll
        for (int mi = 0; mi < 4; mi++)
            #pragma unroll
            for (int ni = 0; ni < 4; ni++)
                acc[mi][ni][0] = acc[mi][ni][1] = acc[mi][ni][2] = acc[mi][ni][3] = 0.f;
        issue(S, W, wrow, Kst, 0);
        for (int kc = 0; kc < nchunk; kc++) {
            if (kc + 1 < nchunk) { issue(S, W, wrow, Kst, kc + 1); CP_WAIT1(); }
            else                 { CP_WAIT0(); }
            __syncthreads();
            compute_chunk(acc, sb + (uint32_t)(kc & 1) * REG + aOff,
                               sb + (2u + (kc & 1)) * REG + bOff);
            __syncthreads();
        }
    };

    auto stash = [&](uint32_t* dst, int bofs, int dosig) {
        #pragma unroll
        for (int ni = 0; ni < 4; ni++) {
            int col = wn * 32 + ni * 8 + ((lane & 3) << 1);
            float2 bv = *(const float2*)(P.bias + bofs + col);
            #pragma unroll
            for (int mi = 0; mi < 4; mi++) {
                #pragma unroll
                for (int half = 0; half < 2; half++) {
                    float vx = acc[mi][ni][half * 2 + 0] + bv.x;
                    float vy = acc[mi][ni][half * 2 + 1] + bv.y;
                    if (dosig) { vx = sigm(vx); vy = sigm(vy); }
                    dst[(mi * 4 + ni) * 2 + half] = packh2(vx, vy);
                }
            }
        }
    };

    // r, z, i tiles
    run_tile(srz, nrz * 2, P.Wrz, 0,   Krz);  stash(rreg, 0,   1);
    run_tile(srz, nrz * 2, P.Wrz, 128, Krz);  stash(zreg, 128, 1);
    run_tile(P.ax, P.nx * 2, P.Win, 0, Kin);  stash(ireg, 256, 0);

    // hn tile + fused pointwise
    const __half* shn[1] = { P.h16 };
    run_tile(shn, 2, P.Whn, 0, 128);

    #pragma unroll
    for (int ni = 0; ni < 4; ni++) {
        int col = wn * 32 + ni * 8 + ((lane & 3) << 1);
        float2 bv = *(const float2*)(P.bias + 384 + col);
        #pragma unroll
        for (int mi = 0; mi < 4; mi++) {
            #pragma unroll
            for (int half = 0; half < 2; half++) {
                int r = bm + wm * 64 + mi * 16 + (lane >> 2) + half * 8;
                if (r >= P.N) continue;
                int idx = (mi * 4 + ni) * 2 + half;
                float2 rv = __half22float2(*(__half2*)&rreg[idx]);
                float2 zv = __half22float2(*(__half2*)&zreg[idx]);
                float2 iv = __half22float2(*(__half2*)&ireg[idx]);
                float hnx = acc[mi][ni][half * 2 + 0] + bv.x;
                float hny = acc[mi][ni][half * 2 + 1] + bv.y;
                float2 hv = *(const float2*)(P.hcur + (size_t)r * 128 + col);
                float ox = (1.f - zv.x) * tanhf(iv.x + rv.x * hnx) + zv.x * hv.x;
                float oy = (1.f - zv.y) * tanhf(iv.y + rv.y * hny) + zv.y * hv.y;
                *(float2*)(P.hout + (size_t)r * 128 + col) = make_float2(ox, oy);
                *(uint32_t*)(P.h16o + (size_t)r * 128 + col) = packh2(ox, oy);
            }
        }
    }
}

// =================== CSR build ===================
__global__ void convert_hist(const void* __restrict__ srcA, const void* __restrict__ srcB,
                             int* __restrict__ dstA, int* __restrict__ dstB,
                             int* __restrict__ cnt, int C, int L, int E)
{
    __shared__ int s_is64;
    if (threadIdx.x == 0) {
        const unsigned* ua = (const unsigned*)srcA;
        const unsigned* ub = (const unsigned*)srcB;
        int n = E < 32 ? E : 32;
        int is64 = 1;
        for (int i = 0; i < n; i++)
            if (ua[2 * i + 1] | ub[2 * i + 1]) { is64 = 0; break; }
        s_is64 = is64;
    }
    __syncthreads();
    int e = blockIdx.x * blockDim.x + threadIdx.x;
    if (e >= E) return;
    int la, ca;
    if (s_is64) {
        la = (int)((const long long*)srcA)[e];
        ca = (int)((const long long*)srcB)[e];
    } else {
        la = ((const int*)srcA)[e];
        ca = ((const int*)srcB)[e];
    }
    dstA[e] = la; dstB[e] = ca;
    if ((unsigned)la < (unsigned)L && (unsigned)ca < (unsigned)C) {
        atomicAdd(&cnt[ca], 1);
        atomicAdd(&cnt[C + la], 1);
    }
}

__global__ void scan_all(const int* __restrict__ cnt, int* __restrict__ off,
                         int* __restrict__ cur, int T)
{
    __shared__ int ws[32];
    int chunk = (T + 1023) >> 10;
    int s = threadIdx.x * chunk;
    int e = min(T, s + chunk);
    int sum = 0;
    for (int i = s; i < e; i++) sum += cnt[i];

    int lane = threadIdx.x & 31, w = threadIdx.x >> 5;
    int x = sum;
    #pragma unroll
    for (int d = 1; d < 32; d <<= 1) {
        int y = __shfl_up_sync(0xffffffffu, x, d);
        if (lane >= d) x += y;
    }
    if (lane == 31) ws[w] = x;
    __syncthreads();
    if (w == 0) {
        int y = ws[lane];
        #pragma unroll
        for (int d = 1; d < 32; d <<= 1) {
            int z = __shfl_up_sync(0xffffffffu, y, d);
            if (lane >= d) y += z;
        }
        ws[lane] = y;
    }
    __syncthreads();
    int excl = x - sum + (w > 0 ? ws[w - 1] : 0);

    int run = excl;
    for (int i = s; i < e; i++) {
        off[i] = run; cur[i] = run;
        run += cnt[i];
    }
    if (s < T && e == T) off[T] = run;
}

__global__ void scatter_edges(const int* __restrict__ lei, const int* __restrict__ cei,
                              int* __restrict__ cur, const int* __restrict__ off,
                              int* __restrict__ permc, int* __restrict__ perml,
                              int C, int L, int E)
{
    int e = blockIdx.x * blockDim.x + threadIdx.x;
    if (e >= E) return;
    int la = lei[e], ca = cei[e];
    if ((unsigned)la >= (unsigned)L || (unsigned)ca >= (unsigned)C) return;
    int p1 = atomicAdd(&cur[ca], 1);
    permc[p1] = la;
    int baseL = off[C];
    int p2 = atomicAdd(&cur[C + la], 1);
    perml[p2 - baseL] = ca;
}

__global__ void seg_sum2(const int* __restrict__ permc, const int* __restrict__ perml,
                         const int* __restrict__ off,
                         const __half* __restrict__ lfeat, const __half* __restrict__ cfeat,
                         __half* __restrict__ caggr, __half* __restrict__ lx0,
                         int C, int T)
{
    int w = (int)(((long long)blockIdx.x * blockDim.x + threadIdx.x) >> 5);
    int lane = threadIdx.x & 31;
    if (w >= T) return;

    const int* perm;
    const __half* feat;
    __half* out;
    int base, dst;
    if (w < C) {
        perm = permc; feat = lfeat; out = caggr; base = 0; dst = w;
    } else {
        perm = perml; feat = cfeat; out = lx0; base = off[C]; dst = w - C;
    }
    int s = off[w] - base, t = off[w + 1] - base;
    float4 acc = make_float4(0.f, 0.f, 0.f, 0.f);
    for (int i = s; i < t; i++) {
        int src = perm[i];
        uint2 v = *(const uint2*)(feat + (size_t)src * 128 + lane * 4);
        float2 f0 = __half22float2(*(__half2*)&v.x);
        float2 f1 = __half22float2(*(__half2*)&v.y);
        acc.x += f0.x; acc.y += f0.y; acc.z += f1.x; acc.w += f1.y;
    }
    uint2 o;
    o.x = packh2(acc.x, acc.y);
    o.y = packh2(acc.z, acc.w);
    *(uint2*)(out + (size_t)dst * 128 + lane * 4) = o;
}

// =================== weight + embedding prep (also zeroes cnt) ===================
struct PrepArgs {
    const float4* mlp[6];
    const float* cWih; const float* cWhh;
    const float* lWih; const float* lWhh;
    const float* cbih; const float* cbhh;
    const float* lbih; const float* lbhh;
    const float4* lemb; const float4* cemb;
    float* lout0; float* cout0;
    int* cnt; int T;
    int L32, C32;
};

__device__ __forceinline__ float wrz_c(const PrepArgs& a, int m, int k) {
    return (k < 128) ? a.cWih[m * 128 + k] : a.cWhh[m * 128 + (k - 128)];
}
__device__ __forceinline__ float wrz_l(const PrepArgs& a, int m, int k) {
    return (k < 256) ? a.lWih[m * 256 + k] : a.lWhh[m * 128 + (k - 256)];
}

#define PQ_MLP  24576
#define PQ_WRZC 16384
#define PQ_WINC 4096
#define PQ_WHNC 4096
#define PQ_WRZL 24576
#define PQ_WINL 8192
#define PQ_WHNL 4096
#define PREP_W  (PQ_MLP + PQ_WRZC + PQ_WINC + PQ_WHNC + PQ_WRZL + PQ_WINL + PQ_WHNL)
#define PREP_TOT (PREP_W + 1024)

__global__ void prep_all(PrepArgs a,
                         __half* __restrict__ mw, __half* __restrict__ gw,
                         float* __restrict__ bcc, float* __restrict__ bcl,
                         __half* __restrict__ l16, __half* __restrict__ c16)
{
    int i = blockIdx.x * blockDim.x + threadIdx.x;

    if (i >= PREP_TOT) {
        long long j = i - PREP_TOT;
        if (j < a.L32) {
            float4 v = a.lemb[j];
            *(uint2*)(l16 + j * 4) = make_uint2(packh2(v.x, v.y), packh2(v.z, v.w));
            ((float4*)a.lout0)[j] = v;
        } else if (j < (long long)a.L32 + a.C32) {
            long long q = j - a.L32;
            float4 v = a.cemb[q];
            *(uint2*)(c16 + q * 4) = make_uint2(packh2(v.x, v.y), packh2(v.z, v.w));
            ((float4*)a.cout0)[q] = v;
        } else {
            long long q = j - a.L32 - a.C32;
            if (q < a.T) a.cnt[q] = 0;
        }
        return;
    }

    float v0, v1, v2, v3;
    __half* o;
    long long obase;

    if (i < PQ_MLP) {
        int midx = i >> 12;
        float4 v = a.mlp[midx][i & 4095];
        v0 = v.x; v1 = v.y; v2 = v.z; v3 = v.w;
        o = mw; obase = (long long)i * 4;
    } else if (i < PQ_MLP + PQ_WRZC) {
        int base = (i - PQ_MLP) * 4, m = base >> 8, k = base & 255;
        v0 = wrz_c(a, m, k);     v1 = wrz_c(a, m, k + 1);
        v2 = wrz_c(a, m, k + 2); v3 = wrz_c(a, m, k + 3);
        o = gw; obase = OFF_WRZC + base;
    } else if (i < PQ_MLP + PQ_WRZC + PQ_WINC) {
        int base = (i - PQ_MLP - PQ_WRZC) * 4, m = base >> 7, k = base & 127;
        const float* s = a.cWih + (256 + m) * 128 + k;
        v0 = s[0]; v1 = s[1]; v2 = s[2]; v3 = s[3];
        o = gw; obase = OFF_WINC + base;
    } else if (i < PQ_MLP + PQ_WRZC + PQ_WINC + PQ_WHNC) {
        int base = (i - PQ_MLP - PQ_WRZC - PQ_WINC) * 4, m = base >> 7, k = base & 127;
        const float* s = a.cWhh + (256 + m) * 128 + k;
        v0 = s[0]; v1 = s[1]; v2 = s[2]; v3 = s[3];
        o = gw; obase = OFF_WHNC + base;
    } else if (i < PQ_MLP + PQ_WRZC + PQ_WINC + PQ_WHNC + PQ_WRZL) {
        int base = (i - PQ_MLP - PQ_WRZC - PQ_WINC - PQ_WHNC) * 4;
        int m = base / 384, k = base % 384;
        v0 = wrz_l(a, m, k);     v1 = wrz_l(a, m, k + 1);
        v2 = wrz_l(a, m, k + 2); v3 = wrz_l(a, m, k + 3);
        o = gw; obase = OFF_WRZL + base;
    } else if (i < PQ_MLP + PQ_WRZC + PQ_WINC + PQ_WHNC + PQ_WRZL + PQ_WINL) {
        int base = (i - PQ_MLP - PQ_WRZC - PQ_WINC - PQ_WHNC - PQ_WRZL) * 4;
        int m = base >> 8, k = base & 255;
        const float* s = a.lWih + (256 + m) * 256 + k;
        v0 = s[0]; v1 = s[1]; v2 = s[2]; v3 = s[3];
        o = gw; obase = OFF_WINL + base;
    } else if (i < PREP_W) {
        int base = (i - (PREP_W - PQ_WHNL)) * 4, m = base >> 7, k = base & 127;
        const float* s = a.lWhh + (256 + m) * 128 + k;
        v0 = s[0]; v1 = s[1]; v2 = s[2]; v3 = s[3];
        o = gw; obase = OFF_WHNL + base;
    } else {
        int j = i - PREP_W;
        if (j < 512) {
            bcc[j] = (j < 256) ? a.cbih[j] + a.cbhh[j]
                   : (j < 384) ? a.cbih[j] : a.cbhh[j - 128];
        } else {
            int m = j - 512;
            bcl[m] = (m < 256) ? a.lbih[m] + a.lbhh[m]
                   : (m < 384) ? a.lbih[m] : a.lbhh[m - 128];
        }
        return;
    }
    *(uint2*)(o + obase) = make_uint2(packh2(v0, v1), packh2(v2, v3));
}

// =================== host side ===================
extern "C" void kernel_launch(void* const* d_in, const int* in_sizes, int n_in,
                              void* d_out, int out_size)
{
    int base = (n_in >= 26) ? 2 : 0;

    const void*  l_ei_raw = d_in[base + 0];
    const void*  c_ei_raw = d_in[base + 1];
    const float* l_emb0   = (const float*)d_in[base + 2];
    const float* c_emb0   = (const float*)d_in[base + 3];

    const float* l2c_W1 = (const float*)d_in[base + 4];
    const float* l2c_b1 = (const float*)d_in[base + 5];
    const float* l2c_W2 = (const float*)d_in[base + 6];
    const float* l2c_b2 = (const float*)d_in[base + 7];
    const float* c2l_W1 = (const float*)d_in[base + 8];
    const float* c2l_b1 = (const float*)d_in[base + 9];
    const float* c2l_W2 = (const float*)d_in[base + 10];
    const float* c2l_b2 = (const float*)d_in[base + 11];
    const float* l2l_W1 = (const float*)d_in[base + 12];
    const float* l2l_b1 = (const float*)d_in[base + 13];
    const float* l2l_W2 = (const float*)d_in[base + 14];
    const float* l2l_b2 = (const float*)d_in[base + 15];
    const float* cgru_Wih = (const float*)d_in[base + 16];
    const float* cgru_Whh = (const float*)d_in[base + 17];
    const float* cgru_bih = (const float*)d_in[base + 18];
    const float* cgru_bhh = (const float*)d_in[base + 19];
    const float* lgru_Wih = (const float*)d_in[base + 20];
    const float* lgru_Whh = (const float*)d_in[base + 21];
    const float* lgru_bih = (const float*)d_in[base + 22];
    const float* lgru_bhh = (const float*)d_in[base + 23];

    const int E = in_sizes[base + 0];
    const int L = in_sizes[base + 2] / DIM;
    const int C = in_sizes[base + 3] / DIM;
    const int T = C + L;

    float* out   = (float*)d_out;
    float* l_out = out;
    float* c_out = out + (size_t)(NITER + 1) * L * DIM;

    __half *lfeat, *cfeat, *caggr, *lx0, *l2lm, *l16, *c16, *mw, *gw;
    float *bcc, *bcl;
    int *lei, *cei, *cnt, *off, *cur, *permc, *perml;
    cudaGetSymbolAddress((void**)&lfeat, g_lfeat);
    cudaGetSymbolAddress((void**)&cfeat, g_cfeat);
    cudaGetSymbolAddress((void**)&caggr, g_caggr);
    cudaGetSymbolAddress((void**)&lx0,   g_lx0);
    cudaGetSymbolAddress((void**)&l2lm,  g_l2lm);
    cudaGetSymbolAddress((void**)&lei,   g_lei32);
    cudaGetSymbolAddress((void**)&cei,   g_cei32);
    cudaGetSymbolAddress((void**)&cnt,   g_cnt);
    cudaGetSymbolAddress((void**)&off,   g_off);
    cudaGetSymbolAddress((void**)&cur,   g_cur);
    cudaGetSymbolAddress((void**)&permc, g_permc);
    cudaGetSymbolAddress((void**)&perml, g_perml);
    cudaGetSymbolAddress((void**)&l16,   g_l16);
    cudaGetSymbolAddress((void**)&c16,   g_c16);
    cudaGetSymbolAddress((void**)&mw,    g_mw16);
    cudaGetSymbolAddress((void**)&gw,    g_gw16);
    cudaGetSymbolAddress((void**)&bcc,   g_bcat_c);
    cudaGetSymbolAddress((void**)&bcl,   g_bcat_l);

    cudaFuncSetAttribute((const void*)fused_mlp3, cudaFuncAttributeMaxDynamicSharedMemorySize, SMEM_MLP);
    cudaFuncSetAttribute((const void*)fused_gru,  cudaFuncAttributeMaxDynamicSharedMemorySize, SMEM_GRU);

    // ---- prelude: 4 kernels ----
    PrepArgs pa;
    pa.mlp[0] = (const float4*)l2c_W1; pa.mlp[1] = (const float4*)l2c_W2;
    pa.mlp[2] = (const float4*)c2l_W1; pa.mlp[3] = (const float4*)c2l_W2;
    pa.mlp[4] = (const float4*)l2l_W1; pa.mlp[5] = (const float4*)l2l_W2;
    pa.cWih = cgru_Wih; pa.cWhh = cgru_Whh;
    pa.lWih = lgru_Wih; pa.lWhh = lgru_Whh;
    pa.cbih = cgru_bih; pa.cbhh = cgru_bhh;
    pa.lbih = lgru_bih; pa.lbhh = lgru_bhh;
    pa.lemb = (const float4*)l_emb0; pa.cemb = (const float4*)c_emb0;
    pa.lout0 = l_out; pa.cout0 = c_out;
    pa.cnt = cnt; pa.T = T;
    pa.L32 = L * 32; pa.C32 = C * 32;
    const int prepN = PREP_TOT + pa.L32 + pa.C32 + T;
    prep_all<<<(prepN + 255) / 256, 256>>>(pa, mw, gw, bcc, bcl, l16, c16);

    convert_hist<<<(E + 255) / 256, 256>>>(l_ei_raw, c_ei_raw, lei, cei, cnt, C, L, E);
    scan_all<<<1, 1024>>>(cnt, off, cur, T);
    scatter_edges<<<(E + 255) / 256, 256>>>(lei, cei, cur, off, permc, perml, C, L, E);

    __half *W_[6];
    for (int i = 0; i < 6; i++) W_[i] = mw + (size_t)i * 16384;

    const int gcC = (C + 127) / 128;
    const int gcL = (L + 127) / 128;
    const int gmax = gcC > gcL ? gcC : gcL;

    for (int it = 0; it < NITER; it++) {
        const float* lcur = l_out + (size_t)it * L * DIM;
        const float* ccur = c_out + (size_t)it * C * DIM;
        float* lnext = l_out + (size_t)(it + 1) * L * DIM;
        float* cnext = c_out + (size_t)(it + 1) * C * DIM;

        // --- 3 MLPs in one launch ---
        MlpP p0{ l16, W_[0], W_[1], l2c_b1, l2c_b2, lfeat, L, 0 };
        MlpP p1{ c16, W_[2], W_[3], c2l_b1, c2l_b2, cfeat, C, 0 };
        MlpP p2{ l16, W_[4], W_[5], l2l_b1, l2l_b2, l2lm,  L, 1 };
        fused_mlp3<<<dim3(gmax, 3), 256, SMEM_MLP>>>(p0, p1, p2);

        // --- merged CSR segment sums ---
        seg_sum2<<<(int)(((long long)T * 32 + 255) / 256), 256>>>(
            permc, perml, off, lfeat, cfeat, caggr, lx0, C, T);

        // --- fully fused GRU (clause + literal in one launch) ---
        GruP Pc, Pl;
        Pc.ax[0] = caggr; Pc.ax[1] = nullptr; Pc.nx = 1;
        Pc.h16 = c16;
        Pc.Wrz = gw + OFF_WRZC; Pc.Win = gw + OFF_WINC; Pc.Whn = gw + OFF_WHNC;
        Pc.bias = bcc; Pc.hcur = ccur; Pc.hout = cnext; Pc.h16o = c16; Pc.N = C;
        Pl.ax[0] = lx0; Pl.ax[1] = l2lm; Pl.nx = 2;
        Pl.h16 = l16;
        Pl.Wrz = gw + OFF_WRZL; Pl.Win = gw + OFF_WINL; Pl.Whn = gw + OFF_WHNL;
        Pl.bias = bcl; Pl.hcur = lcur; Pl.hout = lnext; Pl.h16o = l16; Pl.N = L;
        fused_gru<<<gcC + gcL, 256, SMEM_GRU>>>(Pc, Pl, gcC);
    }
}

// round 14
// speedup vs baseline: 1.1614x; 1.1614x over previous
#include <cuda_runtime.h>
#include <cuda_fp16.h>
#include <math.h>
#include <stdint.h>

#define DIM 128
#define NITER 8

#define MAXL 100096ull
#define MAXC 150016ull
#define MAXE 450048

// ---------------- fp16 intermediates ----------------
__device__ __half g_lfeat[MAXL * 128];
__device__ __half g_cfeat[MAXC * 128];
__device__ __half g_caggr[MAXC * 128];
__device__ __half g_lx0  [MAXL * 128];
__device__ __half g_l2lm [MAXL * 128];
__device__ __half g_gates[(MAXC + MAXL) * 384];  // clause @0, literal @C*384
__device__ int   g_lei32[MAXE];
__device__ int   g_cei32[MAXE];

// ---------------- CSR scratch ----------------
#define MAXT (MAXC + MAXL + 2)
__device__ int g_cnt [MAXT];
__device__ int g_off [MAXT];
__device__ int g_cur [MAXT];
__device__ int g_permc[MAXE];
__device__ int g_perml[MAXE];

// ---------------- fp16 state + weights ----------------
__device__ __half g_l16[MAXL * 128];
__device__ __half g_c16[MAXC * 128];
__device__ __half g_mw16[98304];
__device__ __half g_gw16[245760];
__device__ float  g_bcat_c[512], g_bcat_l[512];

#define OFF_WRZC 0
#define OFF_WINC 65536
#define OFF_WHNC 81920
#define OFF_WRZL 98304
#define OFF_WINL 196608
#define OFF_WHNL 229376

// =================== helpers ===================
__device__ __forceinline__ uint32_t smem_to_u32(const void* p) {
    uint32_t a;
    asm("{ .reg .u64 t; cvta.to.shared.u64 t, %1; cvt.u32.u64 %0, t; }"
        : "=r"(a) : "l"(p));
    return a;
}
__device__ __forceinline__ void cp16(uint32_t dst, const void* src, int sz) {
    asm volatile("cp.async.cg.shared.global [%0], [%1], 16, %2;"
                 :: "r"(dst), "l"(src), "r"(sz));
}
#define CP_COMMIT() asm volatile("cp.async.commit_group;" ::: "memory")
#define CP_WAIT0()  asm volatile("cp.async.wait_group 0;" ::: "memory")
#define CP_WAIT1()  asm volatile("cp.async.wait_group 1;" ::: "memory")

__device__ __forceinline__ void ldx4(uint32_t* r, uint32_t addr) {
    asm volatile("ldmatrix.sync.aligned.m8n8.x4.shared.b16 {%0,%1,%2,%3}, [%4];"
                 : "=r"(r[0]), "=r"(r[1]), "=r"(r[2]), "=r"(r[3]) : "r"(addr));
}
__device__ __forceinline__ void ldx2(uint32_t* r, uint32_t addr) {
    asm volatile("ldmatrix.sync.aligned.m8n8.x2.shared.b16 {%0,%1}, [%2];"
                 : "=r"(r[0]), "=r"(r[1]) : "r"(addr));
}
__device__ __forceinline__ void mma_f16(float* d, const uint32_t* a, const uint32_t* b) {
    asm volatile("mma.sync.aligned.m16n8k16.row.col.f32.f16.f16.f32 "
                 "{%0,%1,%2,%3}, {%4,%5,%6,%7}, {%8,%9}, {%0,%1,%2,%3};"
                 : "+f"(d[0]), "+f"(d[1]), "+f"(d[2]), "+f"(d[3])
                 : "r"(a[0]), "r"(a[1]), "r"(a[2]), "r"(a[3]), "r"(b[0]), "r"(b[1]));
}
__device__ __forceinline__ uint32_t packh2(float x, float y) {
    __half2 p = __floats2half2_rn(x, y);
    return *(uint32_t*)&p;
}
__device__ __forceinline__ float sigm(float x) { return 1.f / (1.f + expf(-x)); }

#define REG 18432u
#define SMEM_GATES (4 * REG)
#define SMEM_MLP   (6 * REG)

__device__ __forceinline__ void compute_chunk(float acc[4][4][4],
                                              uint32_t aBase, uint32_t wBase)
{
    #pragma unroll
    for (int k16 = 0; k16 < 4; k16++) {
        const uint32_t kb = k16 << 5;
        uint32_t af[4][4];
        #pragma unroll
        for (int mi = 0; mi < 4; mi++)
            ldx4(af[mi], aBase + mi * (16 * 144) + kb);
        #pragma unroll
        for (int ni = 0; ni < 4; ni++) {
            uint32_t bf[2];
            ldx2(bf, wBase + ni * (8 * 144) + kb);
            #pragma unroll
            for (int mi = 0; mi < 4; mi++)
                mma_f16(acc[mi][ni], af[mi], bf);
        }
    }
}

// =================== merged 3x fused 2-layer MLP ===================
struct MlpP {
    const __half* A; const __half* W1; const __half* W2;
    const float* b1; const float* b2;
    __half* out; int N; int xr;
};

__global__ __launch_bounds__(256, 2)
void fused_mlp3(MlpP p0, MlpP p1, MlpP p2)
{
    extern __shared__ char smem[];
    const MlpP P = (blockIdx.y == 0) ? p0 : (blockIdx.y == 1) ? p1 : p2;
    const int bm = blockIdx.x * 128;
    if (bm >= P.N) return;

    const uint32_t sb = smem_to_u32(smem);
    const int tid  = threadIdx.x;
    const int lane = tid & 31;
    const int wid  = tid >> 5;
    const int wm   = wid >> 2;
    const int wn   = wid & 3;

    const uint32_t aOff = (uint32_t)(wm * 64 + (lane & 15)) * 144 + ((lane >> 4) << 4);
    const uint32_t bOff = (uint32_t)(wn * 32 + (lane & 7)) * 144 + (((lane >> 3) & 1) << 4);
    const int lrow[4] = { tid >> 3, (tid + 256) >> 3, (tid + 512) >> 3, (tid + 768) >> 3 };
    const int lunit   = tid & 7;

    float acc[4][4][4] = {};

    auto issue1 = [&](int kc) {
        const uint32_t aBuf = sb + (uint32_t)(kc & 1) * REG;
        const uint32_t wBuf = sb + (2u + (kc & 1)) * REG;
        const int k0 = kc << 6;
        #pragma unroll
        for (int t = 0; t < 4; t++) {
            int row = lrow[t];
            uint32_t so = (uint32_t)row * 144 + (lunit << 4);
            int grow = bm + row;
            int ok = grow < P.N;
            int sr = ok ? (P.xr ? (grow ^ 1) : grow) : 0;
            cp16(aBuf + so, P.A + (size_t)sr * 128 + k0 + lunit * 8, ok ? 16 : 0);
            cp16(wBuf + so, P.W1 + (size_t)row * 128 + k0 + lunit * 8, 16);
        }
        CP_COMMIT();
    };

    issue1(0);
    issue1(1);
    CP_WAIT1(); __syncthreads();
    compute_chunk(acc, sb + aOff, sb + 2 * REG + bOff);
    CP_WAIT0(); __syncthreads();
    compute_chunk(acc, sb + REG + aOff, sb + 3 * REG + bOff);
    __syncthreads();

    // prefetch W2 into W0/W1
    #pragma unroll
    for (int kc = 0; kc < 2; kc++) {
        const uint32_t wBuf = sb + (2u + kc) * REG;
        const int k0 = kc << 6;
        #pragma unroll
        for (int t = 0; t < 4; t++) {
            int row = lrow[t];
            uint32_t so = (uint32_t)row * 144 + (lunit << 4);
            cp16(wBuf + so, P.W2 + (size_t)row * 128 + k0 + lunit * 8, 16);
        }
    }
    CP_COMMIT();

    // epilogue 1: relu -> hid H0/H1
    #pragma unroll
    for (int ni = 0; ni < 4; ni++) {
        int c = wn * 32 + ni * 8 + ((lane & 3) << 1);
        float2 bv = *(const float2*)(P.b1 + c);
        uint32_t roff = (4u + (uint32_t)(c >> 6)) * REG + (uint32_t)(c & 63) * 2;
        #pragma unroll
        for (int mi = 0; mi < 4; mi++) {
            int rl0 = wm * 64 + mi * 16 + (lane >> 2);
            float vx0 = fmaxf(acc[mi][ni][0] + bv.x, 0.f);
            float vy0 = fmaxf(acc[mi][ni][1] + bv.y, 0.f);
            float vx1 = fmaxf(acc[mi][ni][2] + bv.x, 0.f);
            float vy1 = fmaxf(acc[mi][ni][3] + bv.y, 0.f);
            *(uint32_t*)(smem + roff + (uint32_t)rl0 * 144)       = packh2(vx0, vy0);
            *(uint32_t*)(smem + roff + (uint32_t)(rl0 + 8) * 144) = packh2(vx1, vy1);
            acc[mi][ni][0] = acc[mi][ni][1] = acc[mi][ni][2] = acc[mi][ni][3] = 0.f;
        }
    }
    CP_WAIT0(); __syncthreads();

    compute_chunk(acc, sb + 4 * REG + aOff, sb + 2 * REG + bOff);
    compute_chunk(acc, sb + 5 * REG + aOff, sb + 3 * REG + bOff);

    #pragma unroll
    for (int ni = 0; ni < 4; ni++) {
        int c = wn * 32 + ni * 8 + ((lane & 3) << 1);
        float2 bv = *(const float2*)(P.b2 + c);
        #pragma unroll
        for (int mi = 0; mi < 4; mi++) {
            int r0 = bm + wm * 64 + mi * 16 + (lane >> 2);
            if (r0 < P.N)
                *(uint32_t*)(P.out + (size_t)r0 * 128 + c) =
                    packh2(acc[mi][ni][0] + bv.x, acc[mi][ni][1] + bv.y);
            if (r0 + 8 < P.N)
                *(uint32_t*)(P.out + (size_t)(r0 + 8) * 128 + c) =
                    packh2(acc[mi][ni][2] + bv.x, acc[mi][ni][3] + bv.y);
        }
    }
}

// =================== combined rz + i_n gates GEMM (clause + literal) ===================
struct GateP {
    const __half* p[3];            // A source list (rz concat order: x.. then h)
    int nx;                        // number of x sources
    const __half* Wrz; const __half* Win;
    const float* bias;
    __half* gates; int N;
};

// grid ((gcC+gcL), 3): y=0,1 -> rz halves (M=256 over two y); y=2 -> i_n.
__global__ __launch_bounds__(256, 2)
void gates2(GateP Pc, GateP Pl, int gcC)
{
    extern __shared__ char smem[];
    const bool isC = (int)blockIdx.x < gcC;
    const GateP P = isC ? Pc : Pl;
    const int bm = (isC ? blockIdx.x : blockIdx.x - gcC) * 128;
    if (bm >= P.N) return;

    const uint32_t sb = smem_to_u32(smem);
    const int tid  = threadIdx.x;
    const int lane = tid & 31;
    const int wid  = tid >> 5;
    const int wm   = wid >> 2;
    const int wn   = wid & 3;
    const int bn   = blockIdx.y * 128;
    const int isIn = (blockIdx.y == 2);
    const __half* W = isIn ? P.Win : P.Wrz;
    const int Krz = (P.nx + 1) * 128;
    const int K   = isIn ? P.nx * 128 : Krz;
    const int wrow = isIn ? 0 : bn;
    const int nchunk = K >> 6;

    float acc[4][4][4] = {};
    const uint32_t aOff = (uint32_t)(wm * 64 + (lane & 15)) * 144 + ((lane >> 4) << 4);
    const uint32_t bOff = (uint32_t)(wn * 32 + (lane & 7)) * 144 + (((lane >> 3) & 1) << 4);
    const int lrow[4] = { tid >> 3, (tid + 256) >> 3, (tid + 512) >> 3, (tid + 768) >> 3 };
    const int lunit   = tid & 7;

    auto issue = [&](int kc) {
        const uint32_t aBuf = sb + (uint32_t)(kc & 1) * REG;
        const uint32_t wBuf = sb + (2u + (kc & 1)) * REG;
        const __half* srcBase = P.p[kc >> 1];
        const int colOfs = ((kc & 1) << 6) + lunit * 8;
        const int k0 = kc << 6;
        #pragma unroll
        for (int t = 0; t < 4; t++) {
            int row = lrow[t];
            uint32_t so = (uint32_t)row * 144 + (lunit << 4);
            int grow = bm + row;
            int ok = grow < P.N;
            cp16(aBuf + so, srcBase + (size_t)(ok ? grow : 0) * 128 + colOfs, ok ? 16 : 0);
            cp16(wBuf + so, W + (size_t)(wrow + row) * K + k0 + lunit * 8, 16);
        }
        CP_COMMIT();
    };

    issue(0);
    for (int kc = 0; kc < nchunk; kc++) {
        if (kc + 1 < nchunk) { issue(kc + 1); CP_WAIT1(); }
        else                 { CP_WAIT0(); }
        __syncthreads();
        compute_chunk(acc, sb + (uint32_t)(kc & 1) * REG + aOff,
                           sb + (2u + (kc & 1)) * REG + bOff);
        __syncthreads();
    }

    #pragma unroll
    for (int ni = 0; ni < 4; ni++) {
        int gcol = bn + wn * 32 + ni * 8 + ((lane & 3) << 1);
        float2 bv = *(const float2*)(P.bias + gcol);
        #pragma unroll
        for (int mi = 0; mi < 4; mi++) {
            int r0 = bm + wm * 64 + mi * 16 + (lane >> 2);
            if (r0 < P.N)
                *(uint32_t*)(P.gates + (size_t)r0 * 384 + gcol) =
                    packh2(acc[mi][ni][0] + bv.x, acc[mi][ni][1] + bv.y);
            if (r0 + 8 < P.N)
                *(uint32_t*)(P.gates + (size_t)(r0 + 8) * 384 + gcol) =
                    packh2(acc[mi][ni][2] + bv.x, acc[mi][ni][3] + bv.y);
        }
    }
}

// =================== combined h_n GEMM + GRU pointwise ===================
struct HnP {
    const __half* h16; const __half* Whn; const float* bias;
    const __half* gates;
    const float* hcur; float* hout; __half* h16o;
    int N;
};

__global__ __launch_bounds__(256, 2)
void hnpw2(HnP Pc, HnP Pl, int gcC)
{
    extern __shared__ char smem[];
    const bool isC = (int)blockIdx.x < gcC;
    const HnP P = isC ? Pc : Pl;
    const int bm = (isC ? blockIdx.x : blockIdx.x - gcC) * 128;
    if (bm >= P.N) return;

    const uint32_t sb = smem_to_u32(smem);
    const int tid  = threadIdx.x;
    const int lane = tid & 31;
    const int wid  = tid >> 5;
    const int wm   = wid >> 2;
    const int wn   = wid & 3;

    float acc[4][4][4] = {};
    const uint32_t aOff = (uint32_t)(wm * 64 + (lane & 15)) * 144 + ((lane >> 4) << 4);
    const uint32_t bOff = (uint32_t)(wn * 32 + (lane & 7)) * 144 + (((lane >> 3) & 1) << 4);
    const int lrow[4] = { tid >> 3, (tid + 256) >> 3, (tid + 512) >> 3, (tid + 768) >> 3 };
    const int lunit   = tid & 7;

    auto issue = [&](int kc) {
        const uint32_t aBuf = sb + (uint32_t)(kc & 1) * REG;
        const uint32_t wBuf = sb + (2u + (kc & 1)) * REG;
        const int k0 = kc << 6;
        #pragma unroll
        for (int t = 0; t < 4; t++) {
            int row = lrow[t];
            uint32_t so = (uint32_t)row * 144 + (lunit << 4);
            int grow = bm + row;
            int ok = grow < P.N;
            cp16(aBuf + so, P.h16 + (size_t)(ok ? grow : 0) * 128 + k0 + lunit * 8, ok ? 16 : 0);
            cp16(wBuf + so, P.Whn + (size_t)row * 128 + k0 + lunit * 8, 16);
        }
        CP_COMMIT();
    };

    issue(0);
    issue(1);
    CP_WAIT1(); __syncthreads();
    compute_chunk(acc, sb + aOff, sb + 2 * REG + bOff);
    CP_WAIT0(); __syncthreads();
    compute_chunk(acc, sb + REG + aOff, sb + 3 * REG + bOff);

    #pragma unroll
    for (int ni = 0; ni < 4; ni++) {
        int col = wn * 32 + ni * 8 + ((lane & 3) << 1);
        float2 bv = *(const float2*)(P.bias + col);
        #pragma unroll
        for (int mi = 0; mi < 4; mi++) {
            int r0 = bm + wm * 64 + mi * 16 + (lane >> 2);
            #pragma unroll
            for (int half = 0; half < 2; half++) {
                int r = r0 + half * 8;
                if (r >= P.N) continue;
                float vx = acc[mi][ni][half * 2 + 0] + bv.x;
                float vy = acc[mi][ni][half * 2 + 1] + bv.y;
                const __half* gp = P.gates + (size_t)r * 384 + col;
                float2 Rv = __half22float2(*(const __half2*)(gp));
                float2 Zv = __half22float2(*(const __half2*)(gp + 128));
                float2 Iv = __half22float2(*(const __half2*)(gp + 256));
                float2 hv = *(const float2*)(P.hcur + (size_t)r * 128 + col);
                float zx = sigm(Zv.x), zy = sigm(Zv.y);
                float ox = (1.f - zx) * tanhf(Iv.x + sigm(Rv.x) * vx) + zx * hv.x;
                float oy = (1.f - zy) * tanhf(Iv.y + sigm(Rv.y) * vy) + zy * hv.y;
                *(float2*)(P.hout + (size_t)r * 128 + col) = make_float2(ox, oy);
                *(uint32_t*)(P.h16o + (size_t)r * 128 + col) = packh2(ox, oy);
            }
        }
    }
}

// =================== CSR build ===================
__global__ void convert_hist(const void* __restrict__ srcA, const void* __restrict__ srcB,
                             int* __restrict__ dstA, int* __restrict__ dstB,
                             int* __restrict__ cnt, int C, int L, int E)
{
    __shared__ int s_is64;
    if (threadIdx.x == 0) {
        const unsigned* ua = (const unsigned*)srcA;
        const unsigned* ub = (const unsigned*)srcB;
        int n = E < 32 ? E : 32;
        int is64 = 1;
        for (int i = 0; i < n; i++)
            if (ua[2 * i + 1] | ub[2 * i + 1]) { is64 = 0; break; }
        s_is64 = is64;
    }
    __syncthreads();
    int e = blockIdx.x * blockDim.x + threadIdx.x;
    if (e >= E) return;
    int la, ca;
    if (s_is64) {
        la = (int)((const long long*)srcA)[e];
        ca = (int)((const long long*)srcB)[e];
    } else {
        la = ((const int*)srcA)[e];
        ca = ((const int*)srcB)[e];
    }
    dstA[e] = la; dstB[e] = ca;
    if ((unsigned)la < (unsigned)L && (unsigned)ca < (unsigned)C) {
        atomicAdd(&cnt[ca], 1);
        atomicAdd(&cnt[C + la], 1);
    }
}

__global__ void scan_all(const int* __restrict__ cnt, int* __restrict__ off,
                         int* __restrict__ cur, int T)
{
    __shared__ int ws[32];
    int chunk = (T + 1023) >> 10;
    int s = threadIdx.x * chunk;
    int e = min(T, s + chunk);
    int sum = 0;
    for (int i = s; i < e; i++) sum += cnt[i];

    int lane = threadIdx.x & 31, w = threadIdx.x >> 5;
    int x = sum;
    #pragma unroll
    for (int d = 1; d < 32; d <<= 1) {
        int y = __shfl_up_sync(0xffffffffu, x, d);
        if (lane >= d) x += y;
    }
    if (lane == 31) ws[w] = x;
    __syncthreads();
    if (w == 0) {
        int y = ws[lane];
        #pragma unroll
        for (int d = 1; d < 32; d <<= 1) {
            int z = __shfl_up_sync(0xffffffffu, y, d);
            if (lane >= d) y += z;
        }
        ws[lane] = y;
    }
    __syncthreads();
    int excl = x - sum + (w > 0 ? ws[w - 1] : 0);

    int run = excl;
    for (int i = s; i < e; i++) {
        off[i] = run; cur[i] = run;
        run += cnt[i];
    }
    if (s < T && e == T) off[T] = run;
}

__global__ void scatter_edges(const int* __restrict__ lei, const int* __restrict__ cei,
                              int* __restrict__ cur, const int* __restrict__ off,
                              int* __restrict__ permc, int* __restrict__ perml,
                              int C, int L, int E)
{
    int e = blockIdx.x * blockDim.x + threadIdx.x;
    if (e >= E) return;
    int la = lei[e], ca = cei[e];
    if ((unsigned)la >= (unsigned)L || (unsigned)ca >= (unsigned)C) return;
    int p1 = atomicAdd(&cur[ca], 1);
    permc[p1] = la;
    int baseL = off[C];
    int p2 = atomicAdd(&cur[C + la], 1);
    perml[p2 - baseL] = ca;
}

__global__ void seg_sum2(const int* __restrict__ permc, const int* __restrict__ perml,
                         const int* __restrict__ off,
                         const __half* __restrict__ lfeat, const __half* __restrict__ cfeat,
                         __half* __restrict__ caggr, __half* __restrict__ lx0,
                         int C, int T)
{
    int w = (int)(((long long)blockIdx.x * blockDim.x + threadIdx.x) >> 5);
    int lane = threadIdx.x & 31;
    if (w >= T) return;

    const int* perm;
    const __half* feat;
    __half* out;
    int base, dst;
    if (w < C) {
        perm = permc; feat = lfeat; out = caggr; base = 0; dst = w;
    } else {
        perm = perml; feat = cfeat; out = lx0; base = off[C]; dst = w - C;
    }
    int s = off[w] - base, t = off[w + 1] - base;
    float4 acc = make_float4(0.f, 0.f, 0.f, 0.f);
    for (int i = s; i < t; i++) {
        int src = perm[i];
        uint2 v = *(const uint2*)(feat + (size_t)src * 128 + lane * 4);
        float2 f0 = __half22float2(*(__half2*)&v.x);
        float2 f1 = __half22float2(*(__half2*)&v.y);
        acc.x += f0.x; acc.y += f0.y; acc.z += f1.x; acc.w += f1.y;
    }
    uint2 o;
    o.x = packh2(acc.x, acc.y);
    o.y = packh2(acc.z, acc.w);
    *(uint2*)(out + (size_t)dst * 128 + lane * 4) = o;
}

// =================== weight + embedding prep (also zeroes cnt) ===================
struct PrepArgs {
    const float4* mlp[6];
    const float* cWih; const float* cWhh;
    const float* lWih; const float* lWhh;
    const float* cbih; const float* cbhh;
    const float* lbih; const float* lbhh;
    const float4* lemb; const float4* cemb;
    float* lout0; float* cout0;
    int* cnt; int T;
    int L32, C32;
};

__device__ __forceinline__ float wrz_c(const PrepArgs& a, int m, int k) {
    return (k < 128) ? a.cWih[m * 128 + k] : a.cWhh[m * 128 + (k - 128)];
}
__device__ __forceinline__ float wrz_l(const PrepArgs& a, int m, int k) {
    return (k < 256) ? a.lWih[m * 256 + k] : a.lWhh[m * 128 + (k - 256)];
}

#define PQ_MLP  24576
#define PQ_WRZC 16384
#define PQ_WINC 4096
#define PQ_WHNC 4096
#define PQ_WRZL 24576
#define PQ_WINL 8192
#define PQ_WHNL 4096
#define PREP_W  (PQ_MLP + PQ_WRZC + PQ_WINC + PQ_WHNC + PQ_WRZL + PQ_WINL + PQ_WHNL)
#define PREP_TOT (PREP_W + 1024)

__global__ void prep_all(PrepArgs a,
                         __half* __restrict__ mw, __half* __restrict__ gw,
                         float* __restrict__ bcc, float* __restrict__ bcl,
                         __half* __restrict__ l16, __half* __restrict__ c16)
{
    int i = blockIdx.x * blockDim.x + threadIdx.x;

    if (i >= PREP_TOT) {
        long long j = i - PREP_TOT;
        if (j < a.L32) {
            float4 v = a.lemb[j];
            *(uint2*)(l16 + j * 4) = make_uint2(packh2(v.x, v.y), packh2(v.z, v.w));
            ((float4*)a.lout0)[j] = v;
        } else if (j < (long long)a.L32 + a.C32) {
            long long q = j - a.L32;
            float4 v = a.cemb[q];
            *(uint2*)(c16 + q * 4) = make_uint2(packh2(v.x, v.y), packh2(v.z, v.w));
            ((float4*)a.cout0)[q] = v;
        } else {
            long long q = j - a.L32 - a.C32;
            if (q < a.T) a.cnt[q] = 0;
        }
        return;
    }

    float v0, v1, v2, v3;
    __half* o;
    long long obase;

    if (i < PQ_MLP) {
        int midx = i >> 12;
        float4 v = a.mlp[midx][i & 4095];
        v0 = v.x; v1 = v.y; v2 = v.z; v3 = v.w;
        o = mw; obase = (long long)i * 4;
    } else if (i < PQ_MLP + PQ_WRZC) {
        int base = (i - PQ_MLP) * 4, m = base >> 8, k = base & 255;
        v0 = wrz_c(a, m, k);     v1 = wrz_c(a, m, k + 1);
        v2 = wrz_c(a, m, k + 2); v3 = wrz_c(a, m, k + 3);
        o = gw; obase = OFF_WRZC + base;
    } else if (i < PQ_MLP + PQ_WRZC + PQ_WINC) {
        int base = (i - PQ_MLP - PQ_WRZC) * 4, m = base >> 7, k = base & 127;
        const float* s = a.cWih + (256 + m) * 128 + k;
        v0 = s[0]; v1 = s[1]; v2 = s[2]; v3 = s[3];
        o = gw; obase = OFF_WINC + base;
    } else if (i < PQ_MLP + PQ_WRZC + PQ_WINC + PQ_WHNC) {
        int base = (i - PQ_MLP - PQ_WRZC - PQ_WINC) * 4, m = base >> 7, k = base & 127;
        const float* s = a.cWhh + (256 + m) * 128 + k;
        v0 = s[0]; v1 = s[1]; v2 = s[2]; v3 = s[3];
        o = gw; obase = OFF_WHNC + base;
    } else if (i < PQ_MLP + PQ_WRZC + PQ_WINC + PQ_WHNC + PQ_WRZL) {
        int base = (i - PQ_MLP - PQ_WRZC - PQ_WINC - PQ_WHNC) * 4;
        int m = base / 384, k = base % 384;
        v0 = wrz_l(a, m, k);     v1 = wrz_l(a, m, k + 1);
        v2 = wrz_l(a, m, k + 2); v3 = wrz_l(a, m, k + 3);
        o = gw; obase = OFF_WRZL + base;
    } else if (i < PQ_MLP + PQ_WRZC + PQ_WINC + PQ_WHNC + PQ_WRZL + PQ_WINL) {
        int base = (i - PQ_MLP - PQ_WRZC - PQ_WINC - PQ_WHNC - PQ_WRZL) * 4;
        int m = base >> 8, k = base & 255;
        const float* s = a.lWih + (256 + m) * 256 + k;
        v0 = s[0]; v1 = s[1]; v2 = s[2]; v3 = s[3];
        o = gw; obase = OFF_WINL + base;
    } else if (i < PREP_W) {
        int base = (i - (PREP_W - PQ_WHNL)) * 4, m = base >> 7, k = base & 127;
        const float* s = a.lWhh + (256 + m) * 128 + k;
        v0 = s[0]; v1 = s[1]; v2 = s[2]; v3 = s[3];
        o = gw; obase = OFF_WHNL + base;
    } else {
        int j = i - PREP_W;
        if (j < 512) {
            bcc[j] = (j < 256) ? a.cbih[j] + a.cbhh[j]
                   : (j < 384) ? a.cbih[j] : a.cbhh[j - 128];
        } else {
            int m = j - 512;
            bcl[m] = (m < 256) ? a.lbih[m] + a.lbhh[m]
                   : (m < 384) ? a.lbih[m] : a.lbhh[m - 128];
        }
        return;
    }
    *(uint2*)(o + obase) = make_uint2(packh2(v0, v1), packh2(v2, v3));
}

// =================== host side ===================
extern "C" void kernel_launch(void* const* d_in, const int* in_sizes, int n_in,
                              void* d_out, int out_size)
{
    int base = (n_in >= 26) ? 2 : 0;

    const void*  l_ei_raw = d_in[base + 0];
    const void*  c_ei_raw = d_in[base + 1];
    const float* l_emb0   = (const float*)d_in[base + 2];
    const float* c_emb0   = (const float*)d_in[base + 3];

    const float* l2c_W1 = (const float*)d_in[base + 4];
    const float* l2c_b1 = (const float*)d_in[base + 5];
    const float* l2c_W2 = (const float*)d_in[base + 6];
    const float* l2c_b2 = (const float*)d_in[base + 7];
    const float* c2l_W1 = (const float*)d_in[base + 8];
    const float* c2l_b1 = (const float*)d_in[base + 9];
    const float* c2l_W2 = (const float*)d_in[base + 10];
    const float* c2l_b2 = (const float*)d_in[base + 11];
    const float* l2l_W1 = (const float*)d_in[base + 12];
    const float* l2l_b1 = (const float*)d_in[base + 13];
    const float* l2l_W2 = (const float*)d_in[base + 14];
    const float* l2l_b2 = (const float*)d_in[base + 15];
    const float* cgru_Wih = (const float*)d_in[base + 16];
    const float* cgru_Whh = (const float*)d_in[base + 17];
    const float* cgru_bih = (const float*)d_in[base + 18];
    const float* cgru_bhh = (const float*)d_in[base + 19];
    const float* lgru_Wih = (const float*)d_in[base + 20];
    const float* lgru_Whh = (const float*)d_in[base + 21];
    const float* lgru_bih = (const float*)d_in[base + 22];
    const float* lgru_bhh = (const float*)d_in[base + 23];

    const int E = in_sizes[base + 0];
    const int L = in_sizes[base + 2] / DIM;
    const int C = in_sizes[base + 3] / DIM;
    const int T = C + L;

    float* out   = (float*)d_out;
    float* l_out = out;
    float* c_out = out + (size_t)(NITER + 1) * L * DIM;

    __half *lfeat, *cfeat, *caggr, *lx0, *l2lm, *gates, *l16, *c16, *mw, *gw;
    float *bcc, *bcl;
    int *lei, *cei, *cnt, *off, *cur, *permc, *perml;
    cudaGetSymbolAddress((void**)&lfeat, g_lfeat);
    cudaGetSymbolAddress((void**)&cfeat, g_cfeat);
    cudaGetSymbolAddress((void**)&caggr, g_caggr);
    cudaGetSymbolAddress((void**)&lx0,   g_lx0);
    cudaGetSymbolAddress((void**)&l2lm,  g_l2lm);
    cudaGetSymbolAddress((void**)&gates, g_gates);
    cudaGetSymbolAddress((void**)&lei,   g_lei32);
    cudaGetSymbolAddress((void**)&cei,   g_cei32);
    cudaGetSymbolAddress((void**)&cnt,   g_cnt);
    cudaGetSymbolAddress((void**)&off,   g_off);
    cudaGetSymbolAddress((void**)&cur,   g_cur);
    cudaGetSymbolAddress((void**)&permc, g_permc);
    cudaGetSymbolAddress((void**)&perml, g_perml);
    cudaGetSymbolAddress((void**)&l16,   g_l16);
    cudaGetSymbolAddress((void**)&c16,   g_c16);
    cudaGetSymbolAddress((void**)&mw,    g_mw16);
    cudaGetSymbolAddress((void**)&gw,    g_gw16);
    cudaGetSymbolAddress((void**)&bcc,   g_bcat_c);
    cudaGetSymbolAddress((void**)&bcl,   g_bcat_l);

    __half* gatesC = gates;
    __half* gatesL = gates + (size_t)C * 384;

    cudaFuncSetAttribute((const void*)fused_mlp3, cudaFuncAttributeMaxDynamicSharedMemorySize, SMEM_MLP);
    cudaFuncSetAttribute((const void*)gates2, cudaFuncAttributeMaxDynamicSharedMemorySize, SMEM_GATES);
    cudaFuncSetAttribute((const void*)hnpw2,  cudaFuncAttributeMaxDynamicSharedMemorySize, SMEM_GATES);

    // ---- prelude: 4 kernels ----
    PrepArgs pa;
    pa.mlp[0] = (const float4*)l2c_W1; pa.mlp[1] = (const float4*)l2c_W2;
    pa.mlp[2] = (const float4*)c2l_W1; pa.mlp[3] = (const float4*)c2l_W2;
    pa.mlp[4] = (const float4*)l2l_W1; pa.mlp[5] = (const float4*)l2l_W2;
    pa.cWih = cgru_Wih; pa.cWhh = cgru_Whh;
    pa.lWih = lgru_Wih; pa.lWhh = lgru_Whh;
    pa.cbih = cgru_bih; pa.cbhh = cgru_bhh;
    pa.lbih = lgru_bih; pa.lbhh = lgru_bhh;
    pa.lemb = (const float4*)l_emb0; pa.cemb = (const float4*)c_emb0;
    pa.lout0 = l_out; pa.cout0 = c_out;
    pa.cnt = cnt; pa.T = T;
    pa.L32 = L * 32; pa.C32 = C * 32;
    const int prepN = PREP_TOT + pa.L32 + pa.C32 + T;
    prep_all<<<(prepN + 255) / 256, 256>>>(pa, mw, gw, bcc, bcl, l16, c16);

    convert_hist<<<(E + 255) / 256, 256>>>(l_ei_raw, c_ei_raw, lei, cei, cnt, C, L, E);
    scan_all<<<1, 1024>>>(cnt, off, cur, T);
    scatter_edges<<<(E + 255) / 256, 256>>>(lei, cei, cur, off, permc, perml, C, L, E);

    __half *W_[6];
    for (int i = 0; i < 6; i++) W_[i] = mw + (size_t)i * 16384;

    const int gcC = (C + 127) / 128;
    const int gcL = (L + 127) / 128;
    const int gmax = gcC > gcL ? gcC : gcL;

    for (int it = 0; it < NITER; it++) {
        const float* lcur = l_out + (size_t)it * L * DIM;
        const float* ccur = c_out + (size_t)it * C * DIM;
        float* lnext = l_out + (size_t)(it + 1) * L * DIM;
        float* cnext = c_out + (size_t)(it + 1) * C * DIM;

        // --- 3 MLPs in one launch ---
        MlpP p0{ l16, W_[0], W_[1], l2c_b1, l2c_b2, lfeat, L, 0 };
        MlpP p1{ c16, W_[2], W_[3], c2l_b1, c2l_b2, cfeat, C, 0 };
        MlpP p2{ l16, W_[4], W_[5], l2l_b1, l2l_b2, l2lm,  L, 1 };
        fused_mlp3<<<dim3(gmax, 3), 256, SMEM_MLP>>>(p0, p1, p2);

        // --- merged CSR segment sums ---
        seg_sum2<<<(int)(((long long)T * 32 + 255) / 256), 256>>>(
            permc, perml, off, lfeat, cfeat, caggr, lx0, C, T);

        // --- GRU gates (clause + literal in one launch) ---
        GateP Gc, Gl;
        Gc.p[0] = caggr; Gc.p[1] = c16; Gc.p[2] = c16; Gc.nx = 1;
        Gc.Wrz = gw + OFF_WRZC; Gc.Win = gw + OFF_WINC;
        Gc.bias = bcc; Gc.gates = gatesC; Gc.N = C;
        Gl.p[0] = lx0; Gl.p[1] = l2lm; Gl.p[2] = l16; Gl.nx = 2;
        Gl.Wrz = gw + OFF_WRZL; Gl.Win = gw + OFF_WINL;
        Gl.bias = bcl; Gl.gates = gatesL; Gl.N = L;
        gates2<<<dim3(gcC + gcL, 3), 256, SMEM_GATES>>>(Gc, Gl, gcC);

        // --- h_n + pointwise (clause + literal in one launch) ---
        HnP Hc, Hl;
        Hc.h16 = c16; Hc.Whn = gw + OFF_WHNC; Hc.bias = bcc + 384;
        Hc.gates = gatesC; Hc.hcur = ccur; Hc.hout = cnext; Hc.h16o = c16; Hc.N = C;
        Hl.h16 = l16; Hl.Whn = gw + OFF_WHNL; Hl.bias = bcl + 384;
        Hl.gates = gatesL; Hl.hcur = lcur; Hl.hout = lnext; Hl.h16o = l16; Hl.N = L;
        hnpw2<<<gcC + gcL, 256, SMEM_GATES>>>(Hc, Hl, gcC);
    }
}

// round 15
// speedup vs baseline: 1.1654x; 1.0034x over previous
#include <cuda_runtime.h>
#include <cuda_fp16.h>
#include <math.h>
#include <stdint.h>

#define DIM 128
#define NITER 8

#define MAXL 100096ull
#define MAXC 150016ull
#define MAXE 450048

// ---------------- fp16 intermediates ----------------
__device__ __half g_lfeat[MAXL * 128];
__device__ __half g_cfeat[MAXC * 128];
__device__ __half g_caggr[MAXC * 128];
__device__ __half g_lx0  [MAXL * 128];
__device__ __half g_l2lm [MAXL * 128];
__device__ __half g_gates[(MAXC + MAXL) * 384];  // clause @0, literal @C*384
__device__ int   g_lei32[MAXE];
__device__ int   g_cei32[MAXE];

// ---------------- CSR scratch ----------------
#define MAXT (MAXC + MAXL + 2)
__device__ int g_cnt [MAXT];
__device__ int g_off [MAXT];
__device__ int g_cur [MAXT];
__device__ int g_permc[MAXE];
__device__ int g_perml[MAXE];

// ---------------- fp16 state + weights ----------------
__device__ __half g_l16[MAXL * 128];
__device__ __half g_c16[MAXC * 128];
__device__ __half g_mw16[98304];
__device__ __half g_gw16[245760];
__device__ float  g_bcat_c[512], g_bcat_l[512];

#define OFF_WRZC 0
#define OFF_WINC 65536
#define OFF_WHNC 81920
#define OFF_WRZL 98304
#define OFF_WINL 196608
#define OFF_WHNL 229376

// =================== helpers ===================
__device__ __forceinline__ uint32_t smem_to_u32(const void* p) {
    uint32_t a;
    asm("{ .reg .u64 t; cvta.to.shared.u64 t, %1; cvt.u32.u64 %0, t; }"
        : "=r"(a) : "l"(p));
    return a;
}
__device__ __forceinline__ void cp16(uint32_t dst, const void* src, int sz) {
    asm volatile("cp.async.cg.shared.global [%0], [%1], 16, %2;"
                 :: "r"(dst), "l"(src), "r"(sz));
}
#define CP_COMMIT() asm volatile("cp.async.commit_group;" ::: "memory")
#define CP_WAIT0()  asm volatile("cp.async.wait_group 0;" ::: "memory")
#define CP_WAIT1()  asm volatile("cp.async.wait_group 1;" ::: "memory")

__device__ __forceinline__ void ldx4(uint32_t* r, uint32_t addr) {
    asm volatile("ldmatrix.sync.aligned.m8n8.x4.shared.b16 {%0,%1,%2,%3}, [%4];"
                 : "=r"(r[0]), "=r"(r[1]), "=r"(r[2]), "=r"(r[3]) : "r"(addr));
}
__device__ __forceinline__ void ldx2(uint32_t* r, uint32_t addr) {
    asm volatile("ldmatrix.sync.aligned.m8n8.x2.shared.b16 {%0,%1}, [%2];"
                 : "=r"(r[0]), "=r"(r[1]) : "r"(addr));
}
__device__ __forceinline__ void mma_f16(float* d, const uint32_t* a, const uint32_t* b) {
    asm volatile("mma.sync.aligned.m16n8k16.row.col.f32.f16.f16.f32 "
                 "{%0,%1,%2,%3}, {%4,%5,%6,%7}, {%8,%9}, {%0,%1,%2,%3};"
                 : "+f"(d[0]), "+f"(d[1]), "+f"(d[2]), "+f"(d[3])
                 : "r"(a[0]), "r"(a[1]), "r"(a[2]), "r"(a[3]), "r"(b[0]), "r"(b[1]));
}
__device__ __forceinline__ uint32_t packh2(float x, float y) {
    __half2 p = __floats2half2_rn(x, y);
    return *(uint32_t*)&p;
}
__device__ __forceinline__ float sigm(float x) { return 1.f / (1.f + expf(-x)); }

#define REG 18432u
#define SMEM_GATES (4 * REG)
#define SMEM_MLP   (6 * REG)

__device__ __forceinline__ void compute_chunk(float acc[4][4][4],
                                              uint32_t aBase, uint32_t wBase)
{
    #pragma unroll
    for (int k16 = 0; k16 < 4; k16++) {
        const uint32_t kb = k16 << 5;
        uint32_t af[4][4];
        #pragma unroll
        for (int mi = 0; mi < 4; mi++)
            ldx4(af[mi], aBase + mi * (16 * 144) + kb);
        #pragma unroll
        for (int ni = 0; ni < 4; ni++) {
            uint32_t bf[2];
            ldx2(bf, wBase + ni * (8 * 144) + kb);
            #pragma unroll
            for (int mi = 0; mi < 4; mi++)
                mma_f16(acc[mi][ni], af[mi], bf);
        }
    }
}

// =================== merged 3x fused 2-layer MLP ===================
struct MlpP {
    const __half* A; const __half* W1; const __half* W2;
    const float* b1; const float* b2;
    __half* out; int N; int xr;
};

__global__ __launch_bounds__(256, 2)
void fused_mlp3(MlpP p0, MlpP p1, MlpP p2)
{
    extern __shared__ char smem[];
    const MlpP P = (blockIdx.y == 0) ? p0 : (blockIdx.y == 1) ? p1 : p2;
    const int bm = blockIdx.x * 128;
    if (bm >= P.N) return;

    const uint32_t sb = smem_to_u32(smem);
    const int tid  = threadIdx.x;
    const int lane = tid & 31;
    const int wid  = tid >> 5;
    const int wm   = wid >> 2;
    const int wn   = wid & 3;

    const uint32_t aOff = (uint32_t)(wm * 64 + (lane & 15)) * 144 + ((lane >> 4) << 4);
    const uint32_t bOff = (uint32_t)(wn * 32 + (lane & 7)) * 144 + (((lane >> 3) & 1) << 4);
    const int lrow[4] = { tid >> 3, (tid + 256) >> 3, (tid + 512) >> 3, (tid + 768) >> 3 };
    const int lunit   = tid & 7;

    float acc[4][4][4] = {};

    auto issue1 = [&](int kc) {
        const uint32_t aBuf = sb + (uint32_t)(kc & 1) * REG;
        const uint32_t wBuf = sb + (2u + (kc & 1)) * REG;
        const int k0 = kc << 6;
        #pragma unroll
        for (int t = 0; t < 4; t++) {
            int row = lrow[t];
            uint32_t so = (uint32_t)row * 144 + (lunit << 4);
            int grow = bm + row;
            int ok = grow < P.N;
            int sr = ok ? (P.xr ? (grow ^ 1) : grow) : 0;
            cp16(aBuf + so, P.A + (size_t)sr * 128 + k0 + lunit * 8, ok ? 16 : 0);
            cp16(wBuf + so, P.W1 + (size_t)row * 128 + k0 + lunit * 8, 16);
        }
        CP_COMMIT();
    };

    issue1(0);
    issue1(1);
    CP_WAIT1(); __syncthreads();
    compute_chunk(acc, sb + aOff, sb + 2 * REG + bOff);
    CP_WAIT0(); __syncthreads();
    compute_chunk(acc, sb + REG + aOff, sb + 3 * REG + bOff);
    __syncthreads();

    // prefetch W2 into W0/W1
    #pragma unroll
    for (int kc = 0; kc < 2; kc++) {
        const uint32_t wBuf = sb + (2u + kc) * REG;
        const int k0 = kc << 6;
        #pragma unroll
        for (int t = 0; t < 4; t++) {
            int row = lrow[t];
            uint32_t so = (uint32_t)row * 144 + (lunit << 4);
            cp16(wBuf + so, P.W2 + (size_t)row * 128 + k0 + lunit * 8, 16);
        }
    }
    CP_COMMIT();

    // epilogue 1: relu -> hid H0/H1
    #pragma unroll
    for (int ni = 0; ni < 4; ni++) {
        int c = wn * 32 + ni * 8 + ((lane & 3) << 1);
        float2 bv = *(const float2*)(P.b1 + c);
        uint32_t roff = (4u + (uint32_t)(c >> 6)) * REG + (uint32_t)(c & 63) * 2;
        #pragma unroll
        for (int mi = 0; mi < 4; mi++) {
            int rl0 = wm * 64 + mi * 16 + (lane >> 2);
            float vx0 = fmaxf(acc[mi][ni][0] + bv.x, 0.f);
            float vy0 = fmaxf(acc[mi][ni][1] + bv.y, 0.f);
            float vx1 = fmaxf(acc[mi][ni][2] + bv.x, 0.f);
            float vy1 = fmaxf(acc[mi][ni][3] + bv.y, 0.f);
            *(uint32_t*)(smem + roff + (uint32_t)rl0 * 144)       = packh2(vx0, vy0);
            *(uint32_t*)(smem + roff + (uint32_t)(rl0 + 8) * 144) = packh2(vx1, vy1);
            acc[mi][ni][0] = acc[mi][ni][1] = acc[mi][ni][2] = acc[mi][ni][3] = 0.f;
        }
    }
    CP_WAIT0(); __syncthreads();

    compute_chunk(acc, sb + 4 * REG + aOff, sb + 2 * REG + bOff);
    compute_chunk(acc, sb + 5 * REG + aOff, sb + 3 * REG + bOff);

    #pragma unroll
    for (int ni = 0; ni < 4; ni++) {
        int c = wn * 32 + ni * 8 + ((lane & 3) << 1);
        float2 bv = *(const float2*)(P.b2 + c);
        #pragma unroll
        for (int mi = 0; mi < 4; mi++) {
            int r0 = bm + wm * 64 + mi * 16 + (lane >> 2);
            if (r0 < P.N)
                *(uint32_t*)(P.out + (size_t)r0 * 128 + c) =
                    packh2(acc[mi][ni][0] + bv.x, acc[mi][ni][1] + bv.y);
            if (r0 + 8 < P.N)
                *(uint32_t*)(P.out + (size_t)(r0 + 8) * 128 + c) =
                    packh2(acc[mi][ni][2] + bv.x, acc[mi][ni][3] + bv.y);
        }
    }
}

// =================== combined rz + i_n gates GEMM (clause + literal) ===================
struct GateP {
    const __half* p[3];
    int nx;
    const __half* Wrz; const __half* Win;
    const float* bias;
    __half* gates; int N;
};

__global__ __launch_bounds__(256, 2)
void gates2(GateP Pc, GateP Pl, int gcC)
{
    extern __shared__ char smem[];
    const bool isC = (int)blockIdx.x < gcC;
    const GateP P = isC ? Pc : Pl;
    const int bm = (isC ? blockIdx.x : blockIdx.x - gcC) * 128;
    if (bm >= P.N) return;

    const uint32_t sb = smem_to_u32(smem);
    const int tid  = threadIdx.x;
    const int lane = tid & 31;
    const int wid  = tid >> 5;
    const int wm   = wid >> 2;
    const int wn   = wid & 3;
    const int bn   = blockIdx.y * 128;
    const int isIn = (blockIdx.y == 2);
    const __half* W = isIn ? P.Win : P.Wrz;
    const int Krz = (P.nx + 1) * 128;
    const int K   = isIn ? P.nx * 128 : Krz;
    const int wrow = isIn ? 0 : bn;
    const int nchunk = K >> 6;

    float acc[4][4][4] = {};
    const uint32_t aOff = (uint32_t)(wm * 64 + (lane & 15)) * 144 + ((lane >> 4) << 4);
    const uint32_t bOff = (uint32_t)(wn * 32 + (lane & 7)) * 144 + (((lane >> 3) & 1) << 4);
    const int lrow[4] = { tid >> 3, (tid + 256) >> 3, (tid + 512) >> 3, (tid + 768) >> 3 };
    const int lunit   = tid & 7;

    auto issue = [&](int kc) {
        const uint32_t aBuf = sb + (uint32_t)(kc & 1) * REG;
        const uint32_t wBuf = sb + (2u + (kc & 1)) * REG;
        const __half* srcBase = P.p[kc >> 1];
        const int colOfs = ((kc & 1) << 6) + lunit * 8;
        const int k0 = kc << 6;
        #pragma unroll
        for (int t = 0; t < 4; t++) {
            int row = lrow[t];
            uint32_t so = (uint32_t)row * 144 + (lunit << 4);
            int grow = bm + row;
            int ok = grow < P.N;
            cp16(aBuf + so, srcBase + (size_t)(ok ? grow : 0) * 128 + colOfs, ok ? 16 : 0);
            cp16(wBuf + so, W + (size_t)(wrow + row) * K + k0 + lunit * 8, 16);
        }
        CP_COMMIT();
    };

    issue(0);
    for (int kc = 0; kc < nchunk; kc++) {
        if (kc + 1 < nchunk) { issue(kc + 1); CP_WAIT1(); }
        else                 { CP_WAIT0(); }
        __syncthreads();
        compute_chunk(acc, sb + (uint32_t)(kc & 1) * REG + aOff,
                           sb + (2u + (kc & 1)) * REG + bOff);
        // trailing sync only needed if buffer (kc&1) gets re-issued (kc+2 exists)
        if (kc + 2 < nchunk) __syncthreads();
    }

    #pragma unroll
    for (int ni = 0; ni < 4; ni++) {
        int gcol = bn + wn * 32 + ni * 8 + ((lane & 3) << 1);
        float2 bv = *(const float2*)(P.bias + gcol);
        #pragma unroll
        for (int mi = 0; mi < 4; mi++) {
            int r0 = bm + wm * 64 + mi * 16 + (lane >> 2);
            if (r0 < P.N)
                *(uint32_t*)(P.gates + (size_t)r0 * 384 + gcol) =
                    packh2(acc[mi][ni][0] + bv.x, acc[mi][ni][1] + bv.y);
            if (r0 + 8 < P.N)
                *(uint32_t*)(P.gates + (size_t)(r0 + 8) * 384 + gcol) =
                    packh2(acc[mi][ni][2] + bv.x, acc[mi][ni][3] + bv.y);
        }
    }
}

// =================== combined h_n GEMM + GRU pointwise ===================
struct HnP {
    const __half* h16; const __half* Whn; const float* bias;
    const __half* gates;
    float* hout; __half* h16o;
    int N;
};

__global__ __launch_bounds__(256, 2)
void hnpw2(HnP Pc, HnP Pl, int gcC)
{
    extern __shared__ char smem[];
    const bool isC = (int)blockIdx.x < gcC;
    const HnP P = isC ? Pc : Pl;
    const int bm = (isC ? blockIdx.x : blockIdx.x - gcC) * 128;
    if (bm >= P.N) return;

    const uint32_t sb = smem_to_u32(smem);
    const int tid  = threadIdx.x;
    const int lane = tid & 31;
    const int wid  = tid >> 5;
    const int wm   = wid >> 2;
    const int wn   = wid & 3;

    float acc[4][4][4] = {};
    const uint32_t aOff = (uint32_t)(wm * 64 + (lane & 15)) * 144 + ((lane >> 4) << 4);
    const uint32_t bOff = (uint32_t)(wn * 32 + (lane & 7)) * 144 + (((lane >> 3) & 1) << 4);
    const int lrow[4] = { tid >> 3, (tid + 256) >> 3, (tid + 512) >> 3, (tid + 768) >> 3 };
    const int lunit   = tid & 7;

    auto issue = [&](int kc) {
        const uint32_t aBuf = sb + (uint32_t)(kc & 1) * REG;
        const uint32_t wBuf = sb + (2u + (kc & 1)) * REG;
        const int k0 = kc << 6;
        #pragma unroll
        for (int t = 0; t < 4; t++) {
            int row = lrow[t];
            uint32_t so = (uint32_t)row * 144 + (lunit << 4);
            int grow = bm + row;
            int ok = grow < P.N;
            cp16(aBuf + so, P.h16 + (size_t)(ok ? grow : 0) * 128 + k0 + lunit * 8, ok ? 16 : 0);
            cp16(wBuf + so, P.Whn + (size_t)row * 128 + k0 + lunit * 8, 16);
        }
        CP_COMMIT();
    };

    issue(0);
    issue(1);
    CP_WAIT1(); __syncthreads();
    compute_chunk(acc, sb + aOff, sb + 2 * REG + bOff);
    CP_WAIT0(); __syncthreads();
    compute_chunk(acc, sb + REG + aOff, sb + 3 * REG + bOff);

    #pragma unroll
    for (int ni = 0; ni < 4; ni++) {
        int col = wn * 32 + ni * 8 + ((lane & 3) << 1);
        float2 bv = *(const float2*)(P.bias + col);
        #pragma unroll
        for (int mi = 0; mi < 4; mi++) {
            int r0 = bm + wm * 64 + mi * 16 + (lane >> 2);
            #pragma unroll
            for (int half = 0; half < 2; half++) {
                int r = r0 + half * 8;
                if (r >= P.N) continue;
                float vx = acc[mi][ni][half * 2 + 0] + bv.x;
                float vy = acc[mi][ni][half * 2 + 1] + bv.y;
                const __half* gp = P.gates + (size_t)r * 384 + col;
                float2 Rv = __half22float2(*(const __half2*)(gp));
                float2 Zv = __half22float2(*(const __half2*)(gp + 128));
                float2 Iv = __half22float2(*(const __half2*)(gp + 256));
                // h carry from fp16 state (same thread reads then overwrites)
                float2 hv = __half22float2(*(const __half2*)(P.h16 + (size_t)r * 128 + col));
                float zx = sigm(Zv.x), zy = sigm(Zv.y);
                float ox = (1.f - zx) * tanhf(Iv.x + sigm(Rv.x) * vx) + zx * hv.x;
                float oy = (1.f - zy) * tanhf(Iv.y + sigm(Rv.y) * vy) + zy * hv.y;
                *(float2*)(P.hout + (size_t)r * 128 + col) = make_float2(ox, oy);
                *(uint32_t*)(P.h16o + (size_t)r * 128 + col) = packh2(ox, oy);
            }
        }
    }
}

// =================== CSR build ===================
__global__ void convert_hist(const void* __restrict__ srcA, const void* __restrict__ srcB,
                             int* __restrict__ dstA, int* __restrict__ dstB,
                             int* __restrict__ cnt, int C, int L, int E)
{
    __shared__ int s_is64;
    if (threadIdx.x == 0) {
        const unsigned* ua = (const unsigned*)srcA;
        const unsigned* ub = (const unsigned*)srcB;
        int n = E < 32 ? E : 32;
        int is64 = 1;
        for (int i = 0; i < n; i++)
            if (ua[2 * i + 1] | ub[2 * i + 1]) { is64 = 0; break; }
        s_is64 = is64;
    }
    __syncthreads();
    int e = blockIdx.x * blockDim.x + threadIdx.x;
    if (e >= E) return;
    int la, ca;
    if (s_is64) {
        la = (int)((const long long*)srcA)[e];
        ca = (int)((const long long*)srcB)[e];
    } else {
        la = ((const int*)srcA)[e];
        ca = ((const int*)srcB)[e];
    }
    dstA[e] = la; dstB[e] = ca;
    if ((unsigned)la < (unsigned)L && (unsigned)ca < (unsigned)C) {
        atomicAdd(&cnt[ca], 1);
        atomicAdd(&cnt[C + la], 1);
    }
}

__global__ void scan_all(const int* __restrict__ cnt, int* __restrict__ off,
                         int* __restrict__ cur, int T)
{
    __shared__ int ws[32];
    int chunk = (T + 1023) >> 10;
    int s = threadIdx.x * chunk;
    int e = min(T, s + chunk);
    int sum = 0;
    for (int i = s; i < e; i++) sum += cnt[i];

    int lane = threadIdx.x & 31, w = threadIdx.x >> 5;
    int x = sum;
    #pragma unroll
    for (int d = 1; d < 32; d <<= 1) {
        int y = __shfl_up_sync(0xffffffffu, x, d);
        if (lane >= d) x += y;
    }
    if (lane == 31) ws[w] = x;
    __syncthreads();
    if (w == 0) {
        int y = ws[lane];
        #pragma unroll
        for (int d = 1; d < 32; d <<= 1) {
            int z = __shfl_up_sync(0xffffffffu, y, d);
            if (lane >= d) y += z;
        }
        ws[lane] = y;
    }
    __syncthreads();
    int excl = x - sum + (w > 0 ? ws[w - 1] : 0);

    int run = excl;
    for (int i = s; i < e; i++) {
        off[i] = run; cur[i] = run;
        run += cnt[i];
    }
    if (s < T && e == T) off[T] = run;
}

__global__ void scatter_edges(const int* __restrict__ lei, const int* __restrict__ cei,
                              int* __restrict__ cur, const int* __restrict__ off,
                              int* __restrict__ permc, int* __restrict__ perml,
                              int C, int L, int E)
{
    int e = blockIdx.x * blockDim.x + threadIdx.x;
    if (e >= E) return;
    int la = lei[e], ca = cei[e];
    if ((unsigned)la >= (unsigned)L || (unsigned)ca >= (unsigned)C) return;
    int p1 = atomicAdd(&cur[ca], 1);
    permc[p1] = la;
    int baseL = off[C];
    int p2 = atomicAdd(&cur[C + la], 1);
    perml[p2 - baseL] = ca;
}

// merged segment sums with index prefetch (batch of 4 breaks load chain)
__global__ void seg_sum2(const int* __restrict__ permc, const int* __restrict__ perml,
                         const int* __restrict__ off,
                         const __half* __restrict__ lfeat, const __half* __restrict__ cfeat,
                         __half* __restrict__ caggr, __half* __restrict__ lx0,
                         int C, int T)
{
    int w = (int)(((long long)blockIdx.x * blockDim.x + threadIdx.x) >> 5);
    int lane = threadIdx.x & 31;
    if (w >= T) return;

    const int* perm;
    const __half* feat;
    __half* out;
    int base, dst;
    if (w < C) {
        perm = permc; feat = lfeat; out = caggr; base = 0; dst = w;
    } else {
        perm = perml; feat = cfeat; out = lx0; base = off[C]; dst = w - C;
    }
    int s = off[w] - base, t = off[w + 1] - base;
    float4 acc = make_float4(0.f, 0.f, 0.f, 0.f);
    int i = s;
    for (; i + 4 <= t; i += 4) {
        int s0 = perm[i], s1 = perm[i + 1], s2 = perm[i + 2], s3 = perm[i + 3];
        uint2 v0 = *(const uint2*)(feat + (size_t)s0 * 128 + lane * 4);
        uint2 v1 = *(const uint2*)(feat + (size_t)s1 * 128 + lane * 4);
        uint2 v2 = *(const uint2*)(feat + (size_t)s2 * 128 + lane * 4);
        uint2 v3 = *(const uint2*)(feat + (size_t)s3 * 128 + lane * 4);
        #define ACC4(v) { \
            float2 f0 = __half22float2(*(__half2*)&(v).x); \
            float2 f1 = __half22float2(*(__half2*)&(v).y); \
            acc.x += f0.x; acc.y += f0.y; acc.z += f1.x; acc.w += f1.y; }
        ACC4(v0) ACC4(v1) ACC4(v2) ACC4(v3)
        #undef ACC4
    }
    for (; i < t; i++) {
        int src = perm[i];
        uint2 v = *(const uint2*)(feat + (size_t)src * 128 + lane * 4);
        float2 f0 = __half22float2(*(__half2*)&v.x);
        float2 f1 = __half22float2(*(__half2*)&v.y);
        acc.x += f0.x; acc.y += f0.y; acc.z += f1.x; acc.w += f1.y;
    }
    uint2 o;
    o.x = packh2(acc.x, acc.y);
    o.y = packh2(acc.z, acc.w);
    *(uint2*)(out + (size_t)dst * 128 + lane * 4) = o;
}

// =================== weight + embedding prep (also zeroes cnt) ===================
struct PrepArgs {
    const float4* mlp[6];
    const float* cWih; const float* cWhh;
    const float* lWih; const float* lWhh;
    const float* cbih; const float* cbhh;
    const float* lbih; const float* lbhh;
    const float4* lemb; const float4* cemb;
    float* lout0; float* cout0;
    int* cnt; int T;
    int L32, C32;
};

__device__ __forceinline__ float wrz_c(const PrepArgs& a, int m, int k) {
    return (k < 128) ? a.cWih[m * 128 + k] : a.cWhh[m * 128 + (k - 128)];
}
__device__ __forceinline__ float wrz_l(const PrepArgs& a, int m, int k) {
    return (k < 256) ? a.lWih[m * 256 + k] : a.lWhh[m * 128 + (k - 256)];
}

#define PQ_MLP  24576
#define PQ_WRZC 16384
#define PQ_WINC 4096
#define PQ_WHNC 4096
#define PQ_WRZL 24576
#define PQ_WINL 8192
#define PQ_WHNL 4096
#define PREP_W  (PQ_MLP + PQ_WRZC + PQ_WINC + PQ_WHNC + PQ_WRZL + PQ_WINL + PQ_WHNL)
#define PREP_TOT (PREP_W + 1024)

__global__ void prep_all(PrepArgs a,
                         __half* __restrict__ mw, __half* __restrict__ gw,
                         float* __restrict__ bcc, float* __restrict__ bcl,
                         __half* __restrict__ l16, __half* __restrict__ c16)
{
    int i = blockIdx.x * blockDim.x + threadIdx.x;

    if (i >= PREP_TOT) {
        long long j = i - PREP_TOT;
        if (j < a.L32) {
            float4 v = a.lemb[j];
            *(uint2*)(l16 + j * 4) = make_uint2(packh2(v.x, v.y), packh2(v.z, v.w));
            ((float4*)a.lout0)[j] = v;
        } else if (j < (long long)a.L32 + a.C32) {
            long long q = j - a.L32;
            float4 v = a.cemb[q];
            *(uint2*)(c16 + q * 4) = make_uint2(packh2(v.x, v.y), packh2(v.z, v.w));
            ((float4*)a.cout0)[q] = v;
        } else {
            long long q = j - a.L32 - a.C32;
            if (q < a.T) a.cnt[q] = 0;
        }
        return;
    }

    float v0, v1, v2, v3;
    __half* o;
    long long obase;

    if (i < PQ_MLP) {
        int midx = i >> 12;
        float4 v = a.mlp[midx][i & 4095];
        v0 = v.x; v1 = v.y; v2 = v.z; v3 = v.w;
        o = mw; obase = (long long)i * 4;
    } else if (i < PQ_MLP + PQ_WRZC) {
        int base = (i - PQ_MLP) * 4, m = base >> 8, k = base & 255;
        v0 = wrz_c(a, m, k);     v1 = wrz_c(a, m, k + 1);
        v2 = wrz_c(a, m, k + 2); v3 = wrz_c(a, m, k + 3);
        o = gw; obase = OFF_WRZC + base;
    } else if (i < PQ_MLP + PQ_WRZC + PQ_WINC) {
        int base = (i - PQ_MLP - PQ_WRZC) * 4, m = base >> 7, k = base & 127;
        const float* s = a.cWih + (256 + m) * 128 + k;
        v0 = s[0]; v1 = s[1]; v2 = s[2]; v3 = s[3];
        o = gw; obase = OFF_WINC + base;
    } else if (i < PQ_MLP + PQ_WRZC + PQ_WINC + PQ_WHNC) {
        int base = (i - PQ_MLP - PQ_WRZC - PQ_WINC) * 4, m = base >> 7, k = base & 127;
        const float* s = a.cWhh + (256 + m) * 128 + k;
        v0 = s[0]; v1 = s[1]; v2 = s[2]; v3 = s[3];
        o = gw; obase = OFF_WHNC + base;
    } else if (i < PQ_MLP + PQ_WRZC + PQ_WINC + PQ_WHNC + PQ_WRZL) {
        int base = (i - PQ_MLP - PQ_WRZC - PQ_WINC - PQ_WHNC) * 4;
        int m = base / 384, k = base % 384;
        v0 = wrz_l(a, m, k);     v1 = wrz_l(a, m, k + 1);
        v2 = wrz_l(a, m, k + 2); v3 = wrz_l(a, m, k + 3);
        o = gw; obase = OFF_WRZL + base;
    } else if (i < PQ_MLP + PQ_WRZC + PQ_WINC + PQ_WHNC + PQ_WRZL + PQ_WINL) {
        int base = (i - PQ_MLP - PQ_WRZC - PQ_WINC - PQ_WHNC - PQ_WRZL) * 4;
        int m = base >> 8, k = base & 255;
        const float* s = a.lWih + (256 + m) * 256 + k;
        v0 = s[0]; v1 = s[1]; v2 = s[2]; v3 = s[3];
        o = gw; obase = OFF_WINL + base;
    } else if (i < PREP_W) {
        int base = (i - (PREP_W - PQ_WHNL)) * 4, m = base >> 7, k = base & 127;
        const float* s = a.lWhh + (256 + m) * 128 + k;
        v0 = s[0]; v1 = s[1]; v2 = s[2]; v3 = s[3];
        o = gw; obase = OFF_WHNL + base;
    } else {
        int j = i - PREP_W;
        if (j < 512) {
            bcc[j] = (j < 256) ? a.cbih[j] + a.cbhh[j]
                   : (j < 384) ? a.cbih[j] : a.cbhh[j - 128];
        } else {
            int m = j - 512;
            bcl[m] = (m < 256) ? a.lbih[m] + a.lbhh[m]
                   : (m < 384) ? a.lbih[m] : a.lbhh[m - 128];
        }
        return;
    }
    *(uint2*)(o + obase) = make_uint2(packh2(v0, v1), packh2(v2, v3));
}

// =================== host side ===================
extern "C" void kernel_launch(void* const* d_in, const int* in_sizes, int n_in,
                              void* d_out, int out_size)
{
    int base = (n_in >= 26) ? 2 : 0;

    const void*  l_ei_raw = d_in[base + 0];
    const void*  c_ei_raw = d_in[base + 1];
    const float* l_emb0   = (const float*)d_in[base + 2];
    const float* c_emb0   = (const float*)d_in[base + 3];

    const float* l2c_W1 = (const float*)d_in[base + 4];
    const float* l2c_b1 = (const float*)d_in[base + 5];
    const float* l2c_W2 = (const float*)d_in[base + 6];
    const float* l2c_b2 = (const float*)d_in[base + 7];
    const float* c2l_W1 = (const float*)d_in[base + 8];
    const float* c2l_b1 = (const float*)d_in[base + 9];
    const float* c2l_W2 = (const float*)d_in[base + 10];
    const float* c2l_b2 = (const float*)d_in[base + 11];
    const float* l2l_W1 = (const float*)d_in[base + 12];
    const float* l2l_b1 = (const float*)d_in[base + 13];
    const float* l2l_W2 = (const float*)d_in[base + 14];
    const float* l2l_b2 = (const float*)d_in[base + 15];
    const float* cgru_Wih = (const float*)d_in[base + 16];
    const float* cgru_Whh = (const float*)d_in[base + 17];
    const float* cgru_bih = (const float*)d_in[base + 18];
    const float* cgru_bhh = (const float*)d_in[base + 19];
    const float* lgru_Wih = (const float*)d_in[base + 20];
    const float* lgru_Whh = (const float*)d_in[base + 21];
    const float* lgru_bih = (const float*)d_in[base + 22];
    const float* lgru_bhh = (const float*)d_in[base + 23];

    const int E = in_sizes[base + 0];
    const int L = in_sizes[base + 2] / DIM;
    const int C = in_sizes[base + 3] / DIM;
    const int T = C + L;

    float* out   = (float*)d_out;
    float* l_out = out;
    float* c_out = out + (size_t)(NITER + 1) * L * DIM;

    __half *lfeat, *cfeat, *caggr, *lx0, *l2lm, *gates, *l16, *c16, *mw, *gw;
    float *bcc, *bcl;
    int *lei, *cei, *cnt, *off, *cur, *permc, *perml;
    cudaGetSymbolAddress((void**)&lfeat, g_lfeat);
    cudaGetSymbolAddress((void**)&cfeat, g_cfeat);
    cudaGetSymbolAddress((void**)&caggr, g_caggr);
    cudaGetSymbolAddress((void**)&lx0,   g_lx0);
    cudaGetSymbolAddress((void**)&l2lm,  g_l2lm);
    cudaGetSymbolAddress((void**)&gates, g_gates);
    cudaGetSymbolAddress((void**)&lei,   g_lei32);
    cudaGetSymbolAddress((void**)&cei,   g_cei32);
    cudaGetSymbolAddress((void**)&cnt,   g_cnt);
    cudaGetSymbolAddress((void**)&off,   g_off);
    cudaGetSymbolAddress((void**)&cur,   g_cur);
    cudaGetSymbolAddress((void**)&permc, g_permc);
    cudaGetSymbolAddress((void**)&perml, g_perml);
    cudaGetSymbolAddress((void**)&l16,   g_l16);
    cudaGetSymbolAddress((void**)&c16,   g_c16);
    cudaGetSymbolAddress((void**)&mw,    g_mw16);
    cudaGetSymbolAddress((void**)&gw,    g_gw16);
    cudaGetSymbolAddress((void**)&bcc,   g_bcat_c);
    cudaGetSymbolAddress((void**)&bcl,   g_bcat_l);

    __half* gatesC = gates;
    __half* gatesL = gates + (size_t)C * 384;

    cudaFuncSetAttribute((const void*)fused_mlp3, cudaFuncAttributeMaxDynamicSharedMemorySize, SMEM_MLP);
    cudaFuncSetAttribute((const void*)gates2, cudaFuncAttributeMaxDynamicSharedMemorySize, SMEM_GATES);
    cudaFuncSetAttribute((const void*)hnpw2,  cudaFuncAttributeMaxDynamicSharedMemorySize, SMEM_GATES);

    // ---- prelude: 4 kernels ----
    PrepArgs pa;
    pa.mlp[0] = (const float4*)l2c_W1; pa.mlp[1] = (const float4*)l2c_W2;
    pa.mlp[2] = (const float4*)c2l_W1; pa.mlp[3] = (const float4*)c2l_W2;
    pa.mlp[4] = (const float4*)l2l_W1; pa.mlp[5] = (const float4*)l2l_W2;
    pa.cWih = cgru_Wih; pa.cWhh = cgru_Whh;
    pa.lWih = lgru_Wih; pa.lWhh = lgru_Whh;
    pa.cbih = cgru_bih; pa.cbhh = cgru_bhh;
    pa.lbih = lgru_bih; pa.lbhh = lgru_bhh;
    pa.lemb = (const float4*)l_emb0; pa.cemb = (const float4*)c_emb0;
    pa.lout0 = l_out; pa.cout0 = c_out;
    pa.cnt = cnt; pa.T = T;
    pa.L32 = L * 32; pa.C32 = C * 32;
    const int prepN = PREP_TOT + pa.L32 + pa.C32 + T;
    prep_all<<<(prepN + 255) / 256, 256>>>(pa, mw, gw, bcc, bcl, l16, c16);

    convert_hist<<<(E + 255) / 256, 256>>>(l_ei_raw, c_ei_raw, lei, cei, cnt, C, L, E);
    scan_all<<<1, 1024>>>(cnt, off, cur, T);
    scatter_edges<<<(E + 255) / 256, 256>>>(lei, cei, cur, off, permc, perml, C, L, E);

    __half *W_[6];
    for (int i = 0; i < 6; i++) W_[i] = mw + (size_t)i * 16384;

    const int gcC = (C + 127) / 128;
    const int gcL = (L + 127) / 128;
    const int gmax = gcC > gcL ? gcC : gcL;

    for (int it = 0; it < NITER; it++) {
        float* lnext = l_out + (size_t)(it + 1) * L * DIM;
        float* cnext = c_out + (size_t)(it + 1) * C * DIM;

        // --- 3 MLPs in one launch ---
        MlpP p0{ l16, W_[0], W_[1], l2c_b1, l2c_b2, lfeat, L, 0 };
        MlpP p1{ c16, W_[2], W_[3], c2l_b1, c2l_b2, cfeat, C, 0 };
        MlpP p2{ l16, W_[4], W_[5], l2l_b1, l2l_b2, l2lm,  L, 1 };
        fused_mlp3<<<dim3(gmax, 3), 256, SMEM_MLP>>>(p0, p1, p2);

        // --- merged CSR segment sums ---
        seg_sum2<<<(int)(((long long)T * 32 + 255) / 256), 256>>>(
            permc, perml, off, lfeat, cfeat, caggr, lx0, C, T);

        // --- GRU gates (clause + literal in one launch) ---
        GateP Gc, Gl;
        Gc.p[0] = caggr; Gc.p[1] = c16; Gc.p[2] = c16; Gc.nx = 1;
        Gc.Wrz = gw + OFF_WRZC; Gc.Win = gw + OFF_WINC;
        Gc.bias = bcc; Gc.gates = gatesC; Gc.N = C;
        Gl.p[0] = lx0; Gl.p[1] = l2lm; Gl.p[2] = l16; Gl.nx = 2;
        Gl.Wrz = gw + OFF_WRZL; Gl.Win = gw + OFF_WINL;
        Gl.bias = bcl; Gl.gates = gatesL; Gl.N = L;
        gates2<<<dim3(gcC + gcL, 3), 256, SMEM_GATES>>>(Gc, Gl, gcC);

        // --- h_n + pointwise (clause + literal in one launch) ---
        HnP Hc, Hl;
        Hc.h16 = c16; Hc.Whn = gw + OFF_WHNC; Hc.bias = bcc + 384;
        Hc.gates = gatesC; Hc.hout = cnext; Hc.h16o = c16; Hc.N = C;
        Hl.h16 = l16; Hl.Whn = gw + OFF_WHNL; Hl.bias = bcl + 384;
        Hl.gates = gatesL; Hl.hout = lnext; Hl.h16o = l16; Hl.N = L;
        hnpw2<<<gcC + gcL, 256, SMEM_GATES>>>(Hc, Hl, gcC);
    }
}

// round 16
// speedup vs baseline: 1.3206x; 1.1332x over previous
#include <cuda_runtime.h>
#include <cuda_fp16.h>
#include <math.h>
#include <stdint.h>

#define DIM 128
#define NITER 8

#define MAXL 100096ull
#define MAXC 150016ull
#define MAXE 450048

// ---------------- fp16 intermediates ----------------
__device__ __half g_lfeat[MAXL * 128];
__device__ __half g_cfeat[MAXC * 128];
__device__ __half g_caggr[MAXC * 128];
__device__ __half g_lx0  [MAXL * 128];
__device__ __half g_l2lm [MAXL * 128];
__device__ __half g_gates[(MAXC + MAXL) * 512];  // [r|z|i|hn], clause @0, literal @C*512
__device__ int   g_lei32[MAXE];
__device__ int   g_cei32[MAXE];

// ---------------- CSR scratch ----------------
#define MAXT (MAXC + MAXL + 2)
__device__ int g_cnt [MAXT];
__device__ int g_off [MAXT];
__device__ int g_cur [MAXT];
__device__ int g_permc[MAXE];
__device__ int g_perml[MAXE];

// ---------------- fp16 state + weights ----------------
__device__ __half g_l16[MAXL * 128];
__device__ __half g_c16[MAXC * 128];
__device__ __half g_mw16[98304];
__device__ __half g_gw16[245760];
__device__ float  g_bcat_c[512], g_bcat_l[512];

#define OFF_WRZC 0
#define OFF_WINC 65536
#define OFF_WHNC 81920
#define OFF_WRZL 98304
#define OFF_WINL 196608
#define OFF_WHNL 229376

// =================== helpers ===================
__device__ __forceinline__ uint32_t smem_to_u32(const void* p) {
    uint32_t a;
    asm("{ .reg .u64 t; cvta.to.shared.u64 t, %1; cvt.u32.u64 %0, t; }"
        : "=r"(a) : "l"(p));
    return a;
}
__device__ __forceinline__ void cp16(uint32_t dst, const void* src, int sz) {
    asm volatile("cp.async.cg.shared.global [%0], [%1], 16, %2;"
                 :: "r"(dst), "l"(src), "r"(sz));
}
#define CP_COMMIT() asm volatile("cp.async.commit_group;" ::: "memory")
#define CP_WAIT0()  asm volatile("cp.async.wait_group 0;" ::: "memory")
#define CP_WAIT1()  asm volatile("cp.async.wait_group 1;" ::: "memory")

__device__ __forceinline__ void ldx4(uint32_t* r, uint32_t addr) {
    asm volatile("ldmatrix.sync.aligned.m8n8.x4.shared.b16 {%0,%1,%2,%3}, [%4];"
                 : "=r"(r[0]), "=r"(r[1]), "=r"(r[2]), "=r"(r[3]) : "r"(addr));
}
__device__ __forceinline__ void ldx2(uint32_t* r, uint32_t addr) {
    asm volatile("ldmatrix.sync.aligned.m8n8.x2.shared.b16 {%0,%1}, [%2];"
                 : "=r"(r[0]), "=r"(r[1]) : "r"(addr));
}
__device__ __forceinline__ void mma_f16(float* d, const uint32_t* a, const uint32_t* b) {
    asm volatile("mma.sync.aligned.m16n8k16.row.col.f32.f16.f16.f32 "
                 "{%0,%1,%2,%3}, {%4,%5,%6,%7}, {%8,%9}, {%0,%1,%2,%3};"
                 : "+f"(d[0]), "+f"(d[1]), "+f"(d[2]), "+f"(d[3])
                 : "r"(a[0]), "r"(a[1]), "r"(a[2]), "r"(a[3]), "r"(b[0]), "r"(b[1]));
}
__device__ __forceinline__ uint32_t packh2(float x, float y) {
    __half2 p = __floats2half2_rn(x, y);
    return *(uint32_t*)&p;
}
__device__ __forceinline__ float sigm(float x) { return 1.f / (1.f + expf(-x)); }

#define REG 18432u
#define SMEM_GATES (4 * REG)
#define SMEM_MLP   (6 * REG)

__device__ __forceinline__ void compute_chunk(float acc[4][4][4],
                                              uint32_t aBase, uint32_t wBase)
{
    #pragma unroll
    for (int k16 = 0; k16 < 4; k16++) {
        const uint32_t kb = k16 << 5;
        uint32_t af[4][4];
        #pragma unroll
        for (int mi = 0; mi < 4; mi++)
            ldx4(af[mi], aBase + mi * (16 * 144) + kb);
        #pragma unroll
        for (int ni = 0; ni < 4; ni++) {
            uint32_t bf[2];
            ldx2(bf, wBase + ni * (8 * 144) + kb);
            #pragma unroll
            for (int mi = 0; mi < 4; mi++)
                mma_f16(acc[mi][ni], af[mi], bf);
        }
    }
}

// =================== merged 3x fused 2-layer MLP ===================
struct MlpP {
    const __half* A; const __half* W1; const __half* W2;
    const float* b1; const float* b2;
    __half* out; int N; int xr;
};

__global__ __launch_bounds__(256, 2)
void fused_mlp3(MlpP p0, MlpP p1, MlpP p2)
{
    extern __shared__ char smem[];
    const MlpP P = (blockIdx.y == 0) ? p0 : (blockIdx.y == 1) ? p1 : p2;
    const int bm = blockIdx.x * 128;
    if (bm >= P.N) return;

    const uint32_t sb = smem_to_u32(smem);
    const int tid  = threadIdx.x;
    const int lane = tid & 31;
    const int wid  = tid >> 5;
    const int wm   = wid >> 2;
    const int wn   = wid & 3;

    const uint32_t aOff = (uint32_t)(wm * 64 + (lane & 15)) * 144 + ((lane >> 4) << 4);
    const uint32_t bOff = (uint32_t)(wn * 32 + (lane & 7)) * 144 + (((lane >> 3) & 1) << 4);
    const int lrow[4] = { tid >> 3, (tid + 256) >> 3, (tid + 512) >> 3, (tid + 768) >> 3 };
    const int lunit   = tid & 7;

    float acc[4][4][4] = {};

    auto issue1 = [&](int kc) {
        const uint32_t aBuf = sb + (uint32_t)(kc & 1) * REG;
        const uint32_t wBuf = sb + (2u + (kc & 1)) * REG;
        const int k0 = kc << 6;
        #pragma unroll
        for (int t = 0; t < 4; t++) {
            int row = lrow[t];
            uint32_t so = (uint32_t)row * 144 + (lunit << 4);
            int grow = bm + row;
            int ok = grow < P.N;
            int sr = ok ? (P.xr ? (grow ^ 1) : grow) : 0;
            cp16(aBuf + so, P.A + (size_t)sr * 128 + k0 + lunit * 8, ok ? 16 : 0);
            cp16(wBuf + so, P.W1 + (size_t)row * 128 + k0 + lunit * 8, 16);
        }
        CP_COMMIT();
    };

    issue1(0);
    issue1(1);
    CP_WAIT1(); __syncthreads();
    compute_chunk(acc, sb + aOff, sb + 2 * REG + bOff);
    CP_WAIT0(); __syncthreads();
    compute_chunk(acc, sb + REG + aOff, sb + 3 * REG + bOff);
    __syncthreads();

    // prefetch W2 into W0/W1
    #pragma unroll
    for (int kc = 0; kc < 2; kc++) {
        const uint32_t wBuf = sb + (2u + kc) * REG;
        const int k0 = kc << 6;
        #pragma unroll
        for (int t = 0; t < 4; t++) {
            int row = lrow[t];
            uint32_t so = (uint32_t)row * 144 + (lunit << 4);
            cp16(wBuf + so, P.W2 + (size_t)row * 128 + k0 + lunit * 8, 16);
        }
    }
    CP_COMMIT();

    // epilogue 1: relu -> hid H0/H1
    #pragma unroll
    for (int ni = 0; ni < 4; ni++) {
        int c = wn * 32 + ni * 8 + ((lane & 3) << 1);
        float2 bv = *(const float2*)(P.b1 + c);
        uint32_t roff = (4u + (uint32_t)(c >> 6)) * REG + (uint32_t)(c & 63) * 2;
        #pragma unroll
        for (int mi = 0; mi < 4; mi++) {
            int rl0 = wm * 64 + mi * 16 + (lane >> 2);
            float vx0 = fmaxf(acc[mi][ni][0] + bv.x, 0.f);
            float vy0 = fmaxf(acc[mi][ni][1] + bv.y, 0.f);
            float vx1 = fmaxf(acc[mi][ni][2] + bv.x, 0.f);
            float vy1 = fmaxf(acc[mi][ni][3] + bv.y, 0.f);
            *(uint32_t*)(smem + roff + (uint32_t)rl0 * 144)       = packh2(vx0, vy0);
            *(uint32_t*)(smem + roff + (uint32_t)(rl0 + 8) * 144) = packh2(vx1, vy1);
            acc[mi][ni][0] = acc[mi][ni][1] = acc[mi][ni][2] = acc[mi][ni][3] = 0.f;
        }
    }
    CP_WAIT0(); __syncthreads();

    compute_chunk(acc, sb + 4 * REG + aOff, sb + 2 * REG + bOff);
    compute_chunk(acc, sb + 5 * REG + aOff, sb + 3 * REG + bOff);

    #pragma unroll
    for (int ni = 0; ni < 4; ni++) {
        int c = wn * 32 + ni * 8 + ((lane & 3) << 1);
        float2 bv = *(const float2*)(P.b2 + c);
        #pragma unroll
        for (int mi = 0; mi < 4; mi++) {
            int r0 = bm + wm * 64 + mi * 16 + (lane >> 2);
            if (r0 < P.N)
                *(uint32_t*)(P.out + (size_t)r0 * 128 + c) =
                    packh2(acc[mi][ni][0] + bv.x, acc[mi][ni][1] + bv.y);
            if (r0 + 8 < P.N)
                *(uint32_t*)(P.out + (size_t)(r0 + 8) * 128 + c) =
                    packh2(acc[mi][ni][2] + bv.x, acc[mi][ni][3] + bv.y);
        }
    }
}

// =================== combined r,z,i,hn gates GEMM (clause + literal) ===================
// grid ((gcC+gcL), 4): y=0,1 -> rz halves; y=2 -> i_n; y=3 -> h_n.
// gates ld = 512, cols [r(128)|z(128)|i(128)|hn(128)], all biases folded.
struct GateP {
    const __half* p[3];            // rz sources: x sources then h (p[nx] = h)
    int nx;
    const __half* Wrz; const __half* Win; const __half* Whn;
    const float* bias;             // 512 entries
    __half* gates; int N;
};

__global__ __launch_bounds__(256, 2)
void gates2(GateP Pc, GateP Pl, int gcC)
{
    extern __shared__ char smem[];
    const bool isC = (int)blockIdx.x < gcC;
    const GateP P = isC ? Pc : Pl;
    const int bm = (isC ? blockIdx.x : blockIdx.x - gcC) * 128;
    if (bm >= P.N) return;

    const uint32_t sb = smem_to_u32(smem);
    const int tid  = threadIdx.x;
    const int lane = tid & 31;
    const int wid  = tid >> 5;
    const int wm   = wid >> 2;
    const int wn   = wid & 3;
    const int yb   = blockIdx.y;
    const int bn   = yb * 128;                 // output column offset (0/128/256/384)
    const int isIn = (yb == 2);
    const int isHn = (yb == 3);
    const __half* W = isHn ? P.Whn : (isIn ? P.Win : P.Wrz);
    const int Krz = (P.nx + 1) * 128;
    const int K   = isHn ? 128 : (isIn ? P.nx * 128 : Krz);
    const int wrow = (yb < 2) ? bn : 0;
    const __half* const* S = isHn ? (P.p + P.nx) : P.p;  // hn reads h only
    const int nchunk = K >> 6;

    float acc[4][4][4] = {};
    const uint32_t aOff = (uint32_t)(wm * 64 + (lane & 15)) * 144 + ((lane >> 4) << 4);
    const uint32_t bOff = (uint32_t)(wn * 32 + (lane & 7)) * 144 + (((lane >> 3) & 1) << 4);
    const int lrow[4] = { tid >> 3, (tid + 256) >> 3, (tid + 512) >> 3, (tid + 768) >> 3 };
    const int lunit   = tid & 7;

    auto issue = [&](int kc) {
        const uint32_t aBuf = sb + (uint32_t)(kc & 1) * REG;
        const uint32_t wBuf = sb + (2u + (kc & 1)) * REG;
        const __half* srcBase = S[kc >> 1];
        const int colOfs = ((kc & 1) << 6) + lunit * 8;
        const int k0 = kc << 6;
        #pragma unroll
        for (int t = 0; t < 4; t++) {
            int row = lrow[t];
            uint32_t so = (uint32_t)row * 144 + (lunit << 4);
            int grow = bm + row;
            int ok = grow < P.N;
            cp16(aBuf + so, srcBase + (size_t)(ok ? grow : 0) * 128 + colOfs, ok ? 16 : 0);
            cp16(wBuf + so, W + (size_t)(wrow + row) * K + k0 + lunit * 8, 16);
        }
        CP_COMMIT();
    };

    issue(0);
    for (int kc = 0; kc < nchunk; kc++) {
        if (kc + 1 < nchunk) { issue(kc + 1); CP_WAIT1(); }
        else                 { CP_WAIT0(); }
        __syncthreads();
        compute_chunk(acc, sb + (uint32_t)(kc & 1) * REG + aOff,
                           sb + (2u + (kc & 1)) * REG + bOff);
        if (kc + 2 < nchunk) __syncthreads();
    }

    #pragma unroll
    for (int ni = 0; ni < 4; ni++) {
        int gcol = bn + wn * 32 + ni * 8 + ((lane & 3) << 1);
        float2 bv = *(const float2*)(P.bias + gcol);
        #pragma unroll
        for (int mi = 0; mi < 4; mi++) {
            int r0 = bm + wm * 64 + mi * 16 + (lane >> 2);
            if (r0 < P.N)
                *(uint32_t*)(P.gates + (size_t)r0 * 512 + gcol) =
                    packh2(acc[mi][ni][0] + bv.x, acc[mi][ni][1] + bv.y);
            if (r0 + 8 < P.N)
                *(uint32_t*)(P.gates + (size_t)(r0 + 8) * 512 + gcol) =
                    packh2(acc[mi][ni][2] + bv.x, acc[mi][ni][3] + bv.y);
        }
    }
}

// =================== GRU pointwise (elementwise only) ===================
__global__ void gru_pw(const __half* __restrict__ gatesC, const __half* __restrict__ gatesL,
                       const __half* __restrict__ c16in, const __half* __restrict__ l16in,
                       float* __restrict__ cnext, float* __restrict__ lnext,
                       __half* __restrict__ c16o, __half* __restrict__ l16o,
                       int C, int T)
{
    long long idx = (long long)blockIdx.x * blockDim.x + threadIdx.x;
    if (idx >= (long long)T * 32) return;
    int n = (int)(idx >> 5);
    int j = (int)(idx & 31) << 2;

    const __half* g; const __half* h; float* ho; __half* h16o; int r;
    if (n < C) { g = gatesC; h = c16in; ho = cnext; h16o = c16o; r = n; }
    else       { g = gatesL; h = l16in; ho = lnext; h16o = l16o; r = n - C; }

    const __half* gp = g + (size_t)r * 512 + j;
    float2 R0 = __half22float2(*(const __half2*)(gp));
    float2 R1 = __half22float2(*(const __half2*)(gp + 2));
    float2 Z0 = __half22float2(*(const __half2*)(gp + 128));
    float2 Z1 = __half22float2(*(const __half2*)(gp + 130));
    float2 I0 = __half22float2(*(const __half2*)(gp + 256));
    float2 I1 = __half22float2(*(const __half2*)(gp + 258));
    float2 H0 = __half22float2(*(const __half2*)(gp + 384));
    float2 H1 = __half22float2(*(const __half2*)(gp + 386));
    float2 h0 = __half22float2(*(const __half2*)(h + (size_t)r * 128 + j));
    float2 h1 = __half22float2(*(const __half2*)(h + (size_t)r * 128 + j + 2));

    float4 o;
    {
        float z = sigm(Z0.x);
        o.x = (1.f - z) * tanhf(I0.x + sigm(R0.x) * H0.x) + z * h0.x;
    }
    {
        float z = sigm(Z0.y);
        o.y = (1.f - z) * tanhf(I0.y + sigm(R0.y) * H0.y) + z * h0.y;
    }
    {
        float z = sigm(Z1.x);
        o.z = (1.f - z) * tanhf(I1.x + sigm(R1.x) * H1.x) + z * h1.x;
    }
    {
        float z = sigm(Z1.y);
        o.w = (1.f - z) * tanhf(I1.y + sigm(R1.y) * H1.y) + z * h1.y;
    }
    *(float4*)(ho + (size_t)r * 128 + j) = o;
    *(uint2*)(h16o + (size_t)r * 128 + j) = make_uint2(packh2(o.x, o.y), packh2(o.z, o.w));
}

// =================== CSR build ===================
__global__ void convert_hist(const void* __restrict__ srcA, const void* __restrict__ srcB,
                             int* __restrict__ dstA, int* __restrict__ dstB,
                             int* __restrict__ cnt, int C, int L, int E)
{
    __shared__ int s_is64;
    if (threadIdx.x == 0) {
        const unsigned* ua = (const unsigned*)srcA;
        const unsigned* ub = (const unsigned*)srcB;
        int n = E < 32 ? E : 32;
        int is64 = 1;
        for (int i = 0; i < n; i++)
            if (ua[2 * i + 1] | ub[2 * i + 1]) { is64 = 0; break; }
        s_is64 = is64;
    }
    __syncthreads();
    int e = blockIdx.x * blockDim.x + threadIdx.x;
    if (e >= E) return;
    int la, ca;
    if (s_is64) {
        la = (int)((const long long*)srcA)[e];
        ca = (int)((const long long*)srcB)[e];
    } else {
        la = ((const int*)srcA)[e];
        ca = ((const int*)srcB)[e];
    }
    dstA[e] = la; dstB[e] = ca;
    if ((unsigned)la < (unsigned)L && (unsigned)ca < (unsigned)C) {
        atomicAdd(&cnt[ca], 1);
        atomicAdd(&cnt[C + la], 1);
    }
}

__global__ void scan_all(const int* __restrict__ cnt, int* __restrict__ off,
                         int* __restrict__ cur, int T)
{
    __shared__ int ws[32];
    int chunk = (T + 1023) >> 10;
    int s = threadIdx.x * chunk;
    int e = min(T, s + chunk);
    int sum = 0;
    for (int i = s; i < e; i++) sum += cnt[i];

    int lane = threadIdx.x & 31, w = threadIdx.x >> 5;
    int x = sum;
    #pragma unroll
    for (int d = 1; d < 32; d <<= 1) {
        int y = __shfl_up_sync(0xffffffffu, x, d);
        if (lane >= d) x += y;
    }
    if (lane == 31) ws[w] = x;
    __syncthreads();
    if (w == 0) {
        int y = ws[lane];
        #pragma unroll
        for (int d = 1; d < 32; d <<= 1) {
            int z = __shfl_up_sync(0xffffffffu, y, d);
            if (lane >= d) y += z;
        }
        ws[lane] = y;
    }
    __syncthreads();
    int excl = x - sum + (w > 0 ? ws[w - 1] : 0);

    int run = excl;
    for (int i = s; i < e; i++) {
        off[i] = run; cur[i] = run;
        run += cnt[i];
    }
    if (s < T && e == T) off[T] = run;
}

__global__ void scatter_edges(const int* __restrict__ lei, const int* __restrict__ cei,
                              int* __restrict__ cur, const int* __restrict__ off,
                              int* __restrict__ permc, int* __restrict__ perml,
                              int C, int L, int E)
{
    int e = blockIdx.x * blockDim.x + threadIdx.x;
    if (e >= E) return;
    int la = lei[e], ca = cei[e];
    if ((unsigned)la >= (unsigned)L || (unsigned)ca >= (unsigned)C) return;
    int p1 = atomicAdd(&cur[ca], 1);
    permc[p1] = la;
    int baseL = off[C];
    int p2 = atomicAdd(&cur[C + la], 1);
    perml[p2 - baseL] = ca;
}

// merged segment sums with index prefetch
__global__ void seg_sum2(const int* __restrict__ permc, const int* __restrict__ perml,
                         const int* __restrict__ off,
                         const __half* __restrict__ lfeat, const __half* __restrict__ cfeat,
                         __half* __restrict__ caggr, __half* __restrict__ lx0,
                         int C, int T)
{
    int w = (int)(((long long)blockIdx.x * blockDim.x + threadIdx.x) >> 5);
    int lane = threadIdx.x & 31;
    if (w >= T) return;

    const int* perm;
    const __half* feat;
    __half* out;
    int base, dst;
    if (w < C) {
        perm = permc; feat = lfeat; out = caggr; base = 0; dst = w;
    } else {
        perm = perml; feat = cfeat; out = lx0; base = off[C]; dst = w - C;
    }
    int s = off[w] - base, t = off[w + 1] - base;
    float4 acc = make_float4(0.f, 0.f, 0.f, 0.f);
    int i = s;
    for (; i + 4 <= t; i += 4) {
        int s0 = perm[i], s1 = perm[i + 1], s2 = perm[i + 2], s3 = perm[i + 3];
        uint2 v0 = *(const uint2*)(feat + (size_t)s0 * 128 + lane * 4);
        uint2 v1 = *(const uint2*)(feat + (size_t)s1 * 128 + lane * 4);
        uint2 v2 = *(const uint2*)(feat + (size_t)s2 * 128 + lane * 4);
        uint2 v3 = *(const uint2*)(feat + (size_t)s3 * 128 + lane * 4);
        #define ACC4(v) { \
            float2 f0 = __half22float2(*(__half2*)&(v).x); \
            float2 f1 = __half22float2(*(__half2*)&(v).y); \
            acc.x += f0.x; acc.y += f0.y; acc.z += f1.x; acc.w += f1.y; }
        ACC4(v0) ACC4(v1) ACC4(v2) ACC4(v3)
        #undef ACC4
    }
    for (; i < t; i++) {
        int src = perm[i];
        uint2 v = *(const uint2*)(feat + (size_t)src * 128 + lane * 4);
        float2 f0 = __half22float2(*(__half2*)&v.x);
        float2 f1 = __half22float2(*(__half2*)&v.y);
        acc.x += f0.x; acc.y += f0.y; acc.z += f1.x; acc.w += f1.y;
    }
    uint2 o;
    o.x = packh2(acc.x, acc.y);
    o.y = packh2(acc.z, acc.w);
    *(uint2*)(out + (size_t)dst * 128 + lane * 4) = o;
}

// =================== weight + embedding prep (also zeroes cnt) ===================
struct PrepArgs {
    const float4* mlp[6];
    const float* cWih; const float* cWhh;
    const float* lWih; const float* lWhh;
    const float* cbih; const float* cbhh;
    const float* lbih; const float* lbhh;
    const float4* lemb; const float4* cemb;
    float* lout0; float* cout0;
    int* cnt; int T;
    int L32, C32;
};

__device__ __forceinline__ float wrz_c(const PrepArgs& a, int m, int k) {
    return (k < 128) ? a.cWih[m * 128 + k] : a.cWhh[m * 128 + (k - 128)];
}
__device__ __forceinline__ float wrz_l(const PrepArgs& a, int m, int k) {
    return (k < 256) ? a.lWih[m * 256 + k] : a.lWhh[m * 128 + (k - 256)];
}

#define PQ_MLP  24576
#define PQ_WRZC 16384
#define PQ_WINC 4096
#define PQ_WHNC 4096
#define PQ_WRZL 24576
#define PQ_WINL 8192
#define PQ_WHNL 4096
#define PREP_W  (PQ_MLP + PQ_WRZC + PQ_WINC + PQ_WHNC + PQ_WRZL + PQ_WINL + PQ_WHNL)
#define PREP_TOT (PREP_W + 1024)

__global__ void prep_all(PrepArgs a,
                         __half* __restrict__ mw, __half* __restrict__ gw,
                         float* __restrict__ bcc, float* __restrict__ bcl,
                         __half* __restrict__ l16, __half* __restrict__ c16)
{
    int i = blockIdx.x * blockDim.x + threadIdx.x;

    if (i >= PREP_TOT) {
        long long j = i - PREP_TOT;
        if (j < a.L32) {
            float4 v = a.lemb[j];
            *(uint2*)(l16 + j * 4) = make_uint2(packh2(v.x, v.y), packh2(v.z, v.w));
            ((float4*)a.lout0)[j] = v;
        } else if (j < (long long)a.L32 + a.C32) {
            long long q = j - a.L32;
            float4 v = a.cemb[q];
            *(uint2*)(c16 + q * 4) = make_uint2(packh2(v.x, v.y), packh2(v.z, v.w));
            ((float4*)a.cout0)[q] = v;
        } else {
            long long q = j - a.L32 - a.C32;
            if (q < a.T) a.cnt[q] = 0;
        }
        return;
    }

    float v0, v1, v2, v3;
    __half* o;
    long long obase;

    if (i < PQ_MLP) {
        int midx = i >> 12;
        float4 v = a.mlp[midx][i & 4095];
        v0 = v.x; v1 = v.y; v2 = v.z; v3 = v.w;
        o = mw; obase = (long long)i * 4;
    } else if (i < PQ_MLP + PQ_WRZC) {
        int base = (i - PQ_MLP) * 4, m = base >> 8, k = base & 255;
        v0 = wrz_c(a, m, k);     v1 = wrz_c(a, m, k + 1);
        v2 = wrz_c(a, m, k + 2); v3 = wrz_c(a, m, k + 3);
        o = gw; obase = OFF_WRZC + base;
    } else if (i < PQ_MLP + PQ_WRZC + PQ_WINC) {
        int base = (i - PQ_MLP - PQ_WRZC) * 4, m = base >> 7, k = base & 127;
        const float* s = a.cWih + (256 + m) * 128 + k;
        v0 = s[0]; v1 = s[1]; v2 = s[2]; v3 = s[3];
        o = gw; obase = OFF_WINC + base;
    } else if (i < PQ_MLP + PQ_WRZC + PQ_WINC + PQ_WHNC) {
        int base = (i - PQ_MLP - PQ_WRZC - PQ_WINC) * 4, m = base >> 7, k = base & 127;
        const float* s = a.cWhh + (256 + m) * 128 + k;
        v0 = s[0]; v1 = s[1]; v2 = s[2]; v3 = s[3];
        o = gw; obase = OFF_WHNC + base;
    } else if (i < PQ_MLP + PQ_WRZC + PQ_WINC + PQ_WHNC + PQ_WRZL) {
        int base = (i - PQ_MLP - PQ_WRZC - PQ_WINC - PQ_WHNC) * 4;
        int m = base / 384, k = base % 384;
        v0 = wrz_l(a, m, k);     v1 = wrz_l(a, m, k + 1);
        v2 = wrz_l(a, m, k + 2); v3 = wrz_l(a, m, k + 3);
        o = gw; obase = OFF_WRZL + base;
    } else if (i < PQ_MLP + PQ_WRZC + PQ_WINC + PQ_WHNC + PQ_WRZL + PQ_WINL) {
        int base = (i - PQ_MLP - PQ_WRZC - PQ_WINC - PQ_WHNC - PQ_WRZL) * 4;
        int m = base >> 8, k = base & 255;
        const float* s = a.lWih + (256 + m) * 256 + k;
        v0 = s[0]; v1 = s[1]; v2 = s[2]; v3 = s[3];
        o = gw; obase = OFF_WINL + base;
    } else if (i < PREP_W) {
        int base = (i - (PREP_W - PQ_WHNL)) * 4, m = base >> 7, k = base & 127;
        const float* s = a.lWhh + (256 + m) * 128 + k;
        v0 = s[0]; v1 = s[1]; v2 = s[2]; v3 = s[3];
        o = gw; obase = OFF_WHNL + base;
    } else {
        int j = i - PREP_W;
        if (j < 512) {
            bcc[j] = (j < 256) ? a.cbih[j] + a.cbhh[j]
                   : (j < 384) ? a.cbih[j] : a.cbhh[j - 128];
        } else {
            int m = j - 512;
            bcl[m] = (m < 256) ? a.lbih[m] + a.lbhh[m]
                   : (m < 384) ? a.lbih[m] : a.lbhh[m - 128];
        }
        return;
    }
    *(uint2*)(o + obase) = make_uint2(packh2(v0, v1), packh2(v2, v3));
}

// =================== host side ===================
extern "C" void kernel_launch(void* const* d_in, const int* in_sizes, int n_in,
                              void* d_out, int out_size)
{
    int base = (n_in >= 26) ? 2 : 0;

    const void*  l_ei_raw = d_in[base + 0];
    const void*  c_ei_raw = d_in[base + 1];
    const float* l_emb0   = (const float*)d_in[base + 2];
    const float* c_emb0   = (const float*)d_in[base + 3];

    const float* l2c_W1 = (const float*)d_in[base + 4];
    const float* l2c_b1 = (const float*)d_in[base + 5];
    const float* l2c_W2 = (const float*)d_in[base + 6];
    const float* l2c_b2 = (const float*)d_in[base + 7];
    const float* c2l_W1 = (const float*)d_in[base + 8];
    const float* c2l_b1 = (const float*)d_in[base + 9];
    const float* c2l_W2 = (const float*)d_in[base + 10];
    const float* c2l_b2 = (const float*)d_in[base + 11];
    const float* l2l_W1 = (const float*)d_in[base + 12];
    const float* l2l_b1 = (const float*)d_in[base + 13];
    const float* l2l_W2 = (const float*)d_in[base + 14];
    const float* l2l_b2 = (const float*)d_in[base + 15];
    const float* cgru_Wih = (const float*)d_in[base + 16];
    const float* cgru_Whh = (const float*)d_in[base + 17];
    const float* cgru_bih = (const float*)d_in[base + 18];
    const float* cgru_bhh = (const float*)d_in[base + 19];
    const float* lgru_Wih = (const float*)d_in[base + 20];
    const float* lgru_Whh = (const float*)d_in[base + 21];
    const float* lgru_bih = (const float*)d_in[base + 22];
    const float* lgru_bhh = (const float*)d_in[base + 23];

    const int E = in_sizes[base + 0];
    const int L = in_sizes[base + 2] / DIM;
    const int C = in_sizes[base + 3] / DIM;
    const int T = C + L;

    float* out   = (float*)d_out;
    float* l_out = out;
    float* c_out = out + (size_t)(NITER + 1) * L * DIM;

    __half *lfeat, *cfeat, *caggr, *lx0, *l2lm, *gates, *l16, *c16, *mw, *gw;
    float *bcc, *bcl;
    int *lei, *cei, *cnt, *off, *cur, *permc, *perml;
    cudaGetSymbolAddress((void**)&lfeat, g_lfeat);
    cudaGetSymbolAddress((void**)&cfeat, g_cfeat);
    cudaGetSymbolAddress((void**)&caggr, g_caggr);
    cudaGetSymbolAddress((void**)&lx0,   g_lx0);
    cudaGetSymbolAddress((void**)&l2lm,  g_l2lm);
    cudaGetSymbolAddress((void**)&gates, g_gates);
    cudaGetSymbolAddress((void**)&lei,   g_lei32);
    cudaGetSymbolAddress((void**)&cei,   g_cei32);
    cudaGetSymbolAddress((void**)&cnt,   g_cnt);
    cudaGetSymbolAddress((void**)&off,   g_off);
    cudaGetSymbolAddress((void**)&cur,   g_cur);
    cudaGetSymbolAddress((void**)&permc, g_permc);
    cudaGetSymbolAddress((void**)&perml, g_perml);
    cudaGetSymbolAddress((void**)&l16,   g_l16);
    cudaGetSymbolAddress((void**)&c16,   g_c16);
    cudaGetSymbolAddress((void**)&mw,    g_mw16);
    cudaGetSymbolAddress((void**)&gw,    g_gw16);
    cudaGetSymbolAddress((void**)&bcc,   g_bcat_c);
    cudaGetSymbolAddress((void**)&bcl,   g_bcat_l);

    __half* gatesC = gates;
    __half* gatesL = gates + (size_t)C * 512;

    cudaFuncSetAttribute((const void*)fused_mlp3, cudaFuncAttributeMaxDynamicSharedMemorySize, SMEM_MLP);
    cudaFuncSetAttribute((const void*)gates2, cudaFuncAttributeMaxDynamicSharedMemorySize, SMEM_GATES);

    // ---- prelude: 4 kernels ----
    PrepArgs pa;
    pa.mlp[0] = (const float4*)l2c_W1; pa.mlp[1] = (const float4*)l2c_W2;
    pa.mlp[2] = (const float4*)c2l_W1; pa.mlp[3] = (const float4*)c2l_W2;
    pa.mlp[4] = (const float4*)l2l_W1; pa.mlp[5] = (const float4*)l2l_W2;
    pa.cWih = cgru_Wih; pa.cWhh = cgru_Whh;
    pa.lWih = lgru_Wih; pa.lWhh = lgru_Whh;
    pa.cbih = cgru_bih; pa.cbhh = cgru_bhh;
    pa.lbih = lgru_bih; pa.lbhh = lgru_bhh;
    pa.lemb = (const float4*)l_emb0; pa.cemb = (const float4*)c_emb0;
    pa.lout0 = l_out; pa.cout0 = c_out;
    pa.cnt = cnt; pa.T = T;
    pa.L32 = L * 32; pa.C32 = C * 32;
    const int prepN = PREP_TOT + pa.L32 + pa.C32 + T;
    prep_all<<<(prepN + 255) / 256, 256>>>(pa, mw, gw, bcc, bcl, l16, c16);

    convert_hist<<<(E + 255) / 256, 256>>>(l_ei_raw, c_ei_raw, lei, cei, cnt, C, L, E);
    scan_all<<<1, 1024>>>(cnt, off, cur, T);
    scatter_edges<<<(E + 255) / 256, 256>>>(lei, cei, cur, off, permc, perml, C, L, E);

    __half *W_[6];
    for (int i = 0; i < 6; i++) W_[i] = mw + (size_t)i * 16384;

    const int gcC = (C + 127) / 128;
    const int gcL = (L + 127) / 128;
    const int gmax = gcC > gcL ? gcC : gcL;

    for (int it = 0; it < NITER; it++) {
        float* lnext = l_out + (size_t)(it + 1) * L * DIM;
        float* cnext = c_out + (size_t)(it + 1) * C * DIM;

        // --- 3 MLPs in one launch ---
        MlpP p0{ l16, W_[0], W_[1], l2c_b1, l2c_b2, lfeat, L, 0 };
        MlpP p1{ c16, W_[2], W_[3], c2l_b1, c2l_b2, cfeat, C, 0 };
        MlpP p2{ l16, W_[4], W_[5], l2l_b1, l2l_b2, l2lm,  L, 1 };
        fused_mlp3<<<dim3(gmax, 3), 256, SMEM_MLP>>>(p0, p1, p2);

        // --- merged CSR segment sums ---
        seg_sum2<<<(int)(((long long)T * 32 + 255) / 256), 256>>>(
            permc, perml, off, lfeat, cfeat, caggr, lx0, C, T);

        // --- GRU gates r,z,i,hn (clause + literal, one launch, hn overlapped) ---
        GateP Gc, Gl;
        Gc.p[0] = caggr; Gc.p[1] = c16; Gc.p[2] = c16; Gc.nx = 1;
        Gc.Wrz = gw + OFF_WRZC; Gc.Win = gw + OFF_WINC; Gc.Whn = gw + OFF_WHNC;
        Gc.bias = bcc; Gc.gates = gatesC; Gc.N = C;
        Gl.p[0] = lx0; Gl.p[1] = l2lm; Gl.p[2] = l16; Gl.nx = 2;
        Gl.Wrz = gw + OFF_WRZL; Gl.Win = gw + OFF_WINL; Gl.Whn = gw + OFF_WHNL;
        Gl.bias = bcl; Gl.gates = gatesL; Gl.N = L;
        gates2<<<dim3(gcC + gcL, 4), 256, SMEM_GATES>>>(Gc, Gl, gcC);

        // --- GRU pointwise (elementwise) ---
        gru_pw<<<(int)(((long long)T * 32 + 255) / 256), 256>>>(
            gatesC, gatesL, c16, l16, cnext, lnext, c16, l16, C, T);
    }
}